// round 10
// baseline (speedup 1.0000x reference)
#include <cuda_runtime.h>
#include <math.h>

// ---------------- static scratch ----------------
#define SMAX   65
#define NMAXV  (SMAX*SMAX*SMAX)       // 274625 vertices
#define NWPAD  8832                   // occ bit-words + pad
#define NGMAX  9216                   // 32-anchor edge groups (padded)
#define NCMAX  (64*64*64)             // cubes
#define TMAXT  (6*NCMAX)              // tets
#define EMAXE  (7*NMAXV)              // edge slots
#define SCAN_B 256
#define SCAN_I 8
#define TCH    (SCAN_B*SCAN_I)        // 2048 tets per chunk
#define MAXCH  1024

__device__ unsigned           g_occw[NWPAD];
__device__ float              g_sdf[NMAXV];
__device__ float              g_rot[3*NMAXV];
__device__ uint4              g_egrp[NGMAX*2];    // 7 masks + exclusive base
__device__ int                g_eGrpCnt[NGMAX];
__device__ unsigned char      g_cubeCode[NCMAX];
__device__ int                g_edgeRank[EMAXE];  // rank per crossing edge slot
__device__ int                g_edgeList[EMAXE];  // packed (v<<3)|type per rank
__device__ unsigned           g_tetScan[TMAXT];   // packed (cnt1 lo16 | cnt2 hi16)
__device__ unsigned           g_tBlkP[MAXCH];
__device__ unsigned long long g_tBlk64[MAXCH];
__device__ int                g_nv;
__device__ int                g_n1;
__device__ unsigned           g_done1;            // last-block counters (self-reset)
__device__ unsigned           g_done2;

__constant__ int c_path[6][4] = {
    {0,4,6,7},{0,4,5,7},{0,2,6,7},{0,2,3,7},{0,1,5,7},{0,1,3,7}};
__constant__ int c_ntri[16] = {0,1,1,2,1,2,2,1,1,2,2,1,2,1,1,0};
__constant__ int c_tri[16][6] = {
    {-1,-1,-1,-1,-1,-1},
    { 1, 0, 2,-1,-1,-1},
    { 4, 0, 3,-1,-1,-1},
    { 1, 4, 2, 1, 3, 4},
    { 3, 1, 5,-1,-1,-1},
    { 2, 3, 0, 2, 5, 3},
    { 1, 4, 0, 1, 5, 4},
    { 4, 2, 5,-1,-1,-1},
    { 4, 5, 2,-1,-1,-1},
    { 4, 1, 0, 4, 5, 1},
    { 3, 2, 0, 3, 5, 2},
    { 1, 3, 5,-1,-1,-1},
    { 4, 1, 2, 4, 3, 1},
    { 3, 0, 4,-1,-1,-1},
    { 2, 0, 1,-1,-1,-1},
    {-1,-1,-1,-1,-1,-1}};

__device__ __forceinline__ unsigned bits32(int b)
{
    unsigned w0 = g_occw[b >> 5];
    unsigned w1 = g_occw[(b >> 5) + 1];
    return __funnelshift_r(w0, w1, b & 31);
}

// shuffle-based exclusive block scan; ALL 32 lanes of warp 0 run the reduction
// shuffles (partial-warp shuffle with full mask hangs). Trailing sync: loop-safe.
template<int NT>
__device__ __forceinline__ unsigned blk_exscan_u32(unsigned v, int tid, unsigned* tot)
{
    constexpr int NW = NT/32;
    __shared__ unsigned ws[NW];
    int lane = tid & 31, w = tid >> 5;
    unsigned x = v;
#pragma unroll
    for (int o = 1; o < 32; o <<= 1) {
        unsigned y = __shfl_up_sync(0xffffffffu, x, o);
        if (lane >= o) x += y;
    }
    if (lane == 31) ws[w] = x;
    __syncthreads();
    if (w == 0) {
        unsigned t = (lane < NW) ? ws[lane] : 0u;
#pragma unroll
        for (int o = 1; o < NW; o <<= 1) {
            unsigned y = __shfl_up_sync(0xffffffffu, t, o);
            if (lane >= o) t += y;
        }
        if (lane < NW) ws[lane] = t;
    }
    __syncthreads();
    unsigned base = w ? ws[w-1] : 0u;
    *tot = ws[NW - 1];
    __syncthreads();
    return base + x - v;
}

template<int NT>
__device__ __forceinline__ unsigned long long blk_exscan_u64(unsigned long long v, int tid,
                                                             unsigned long long* tot)
{
    constexpr int NW = NT/32;
    __shared__ unsigned long long ws[NW];
    int lane = tid & 31, w = tid >> 5;
    unsigned long long x = v;
#pragma unroll
    for (int o = 1; o < 32; o <<= 1) {
        unsigned long long y = __shfl_up_sync(0xffffffffu, x, o);
        if (lane >= o) x += y;
    }
    if (lane == 31) ws[w] = x;
    __syncthreads();
    if (w == 0) {
        unsigned long long t = (lane < NW) ? ws[lane] : 0ull;
#pragma unroll
        for (int o = 1; o < NW; o <<= 1) {
            unsigned long long y = __shfl_up_sync(0xffffffffu, t, o);
            if (lane >= o) t += y;
        }
        if (lane < NW) ws[lane] = t;
    }
    __syncthreads();
    unsigned long long base = w ? ws[w-1] : 0ull;
    *tot = ws[NW - 1];
    __syncthreads();
    return base + x - v;
}

// last-block-done: returns true in exactly one block after all blocks arrive.
__device__ __forceinline__ bool last_block(unsigned* ctr, unsigned nb)
{
    __shared__ unsigned s_last;
    __threadfence();
    __syncthreads();
    if (threadIdx.x == 0) {
        unsigned prev = atomicAdd(ctr, 1u);
        if (prev == nb - 1u) { *ctr = 0u; s_last = 1u; }   // self-reset for replay
        else                 s_last = 0u;
    }
    __syncthreads();
    return s_last != 0u;
}

// ---------------- kernel 1: per-vertex prep + occ bit-pack ----------------
__global__ void k_prep(const float* __restrict__ sdf_n,
                       const float* __restrict__ dir,
                       const float* __restrict__ rotm,
                       const float* __restrict__ scales,
                       int N, float dscale)
{
    int v = blockIdx.x*blockDim.x + threadIdx.x;
    bool inb = v < N;
    float s = inb ? sdf_n[v] : -1.0f;
    unsigned bal = __ballot_sync(0xffffffffu, s > 0.0f);
    if ((threadIdx.x & 31) == 0) g_occw[v >> 5] = bal;
    if (!inb) return;

    g_sdf[v] = tanhf(s);
    float l0 = dscale * tanhf(dir[2*v+0]);
    float l1 = dscale * tanhf(dir[2*v+1]);
    const float* m = rotm + 9*(size_t)v;
    float sc = scales[v];
    g_rot[3*v+0] = (m[0]*l0 + m[3]*l1 + m[6]) * sc;
    g_rot[3*v+1] = (m[1]*l0 + m[4]*l1 + m[7]) * sc;
    g_rot[3*v+2] = (m[2]*l0 + m[5]*l1 + m[8]) * sc;
}

// ---------------- kernel 2: masks + counts + cube codes; last block scans ----------------
__global__ void k_grp(int N, int S, int NG, int NC, int R)
{
    int t = blockIdx.x*blockDim.x + threadIdx.x;
    int S2 = S*S;

    if (t < NG) {
        int v0 = t << 5;
        int i0 = v0 / S2; int rem = v0 - i0*S2; int j0 = rem / S; int k0 = rem - j0*S;
        int qw = S - k0;
        unsigned pre = (qw >= 32) ? 0xffffffffu : ((1u << (qw & 31)) - 1u);
        int j1 = j0 + 1, i1 = i0; if (j1 == S) { j1 = 0; ++i1; }
        int nvld = N - v0;
        unsigned tailm = (nvld >= 32) ? 0xffffffffu : ((1u << (nvld & 31)) - 1u);
        unsigned A = bits32(v0);
        unsigned mm[7]; int cnt = 0;
#pragma unroll
        for (int tt = 1; tt <= 7; ++tt) {
            int di = (tt>>2)&1, dj = (tt>>1)&1, dk = tt&1;
            int d = di*S2 + dj*S + dk;
            unsigned X = A ^ bits32(v0 + d);
            unsigned vm = (((i0+di < S) && (j0+dj < S)) ? pre : 0u)
                        | (((i1+di < S) && (j1+dj < S)) ? ~pre : 0u);
            if (dk && (qw - 1) < 32) vm &= ~(1u << (qw - 1));
            vm &= tailm;
            mm[tt-1] = X & vm;
            cnt += __popc(mm[tt-1]);
        }
        g_egrp[2*t]   = make_uint4(mm[0], mm[1], mm[2], mm[3]);
        g_egrp[2*t+1] = make_uint4(mm[4], mm[5], mm[6], 0u);
        g_eGrpCnt[t]  = cnt;
    }

    if (t < NC) {
        int R2 = R*R;
        int i = t / R2; int rem = t - i*R2; int j = rem / R; int k = rem - j*R;
        int b = (i*S + j)*S + k;
        unsigned p00 = bits32(b)          & 3u;
        unsigned p01 = bits32(b + S)      & 3u;
        unsigned p10 = bits32(b + S2)     & 3u;
        unsigned p11 = bits32(b + S2 + S) & 3u;
        g_cubeCode[t] = (unsigned char)(p00 | (p01 << 2) | (p10 << 4) | (p11 << 6));
    }

    // last arriving block: exclusive scan over group counts (L2-hot)
    if (last_block(&g_done1, gridDim.x)) {
        int tid = threadIdx.x;
        int K = (NG + SCAN_B - 1) / SCAN_B;
        int base = tid * K;
        int run = 0;
        for (int it = 0; it < K; ++it) {
            int idx = base + it;
            if (idx < NG) run += g_eGrpCnt[idx];
        }
        unsigned tot;
        unsigned exc = blk_exscan_u32<SCAN_B>((unsigned)run, tid, &tot);
        int acc = (int)exc;
        for (int it = 0; it < K; ++it) {
            int idx = base + it;
            if (idx < NG) {
                int c = g_eGrpCnt[idx];
                ((unsigned*)g_egrp)[idx*8 + 7] = (unsigned)acc;
                acc += c;
            }
        }
        if (tid == 0) g_nv = (int)tot;
    }
}

// ---------------- kernel 3: edge ranks (warp/group) + tet scan; last block scans chunks ----------------
__global__ void k_rankscan(int NG, int nRB, int T, int R, int nCh, int S)
{
    int tid = threadIdx.x;

    if (blockIdx.x < nRB) {
        // ---- rank part: one warp per 32-anchor group ----
        int g = blockIdx.x*8 + (tid >> 5);
        if (g < NG) {
            int lane = tid & 31;
            uint4 Aa = g_egrp[2*g], Bb = g_egrp[2*g+1];
            unsigned mm[7] = {Aa.x, Aa.y, Aa.z, Aa.w, Bb.x, Bb.y, Bb.z};
            unsigned low = (1u << lane) - 1u;
            int cum = (int)Bb.w;
#pragma unroll
            for (int x = 0; x < 7; ++x) cum += __popc(mm[x] & low);
            int v = (g << 5) + lane;
            int e = v*7;
            int part = 0;
#pragma unroll
            for (int t = 0; t < 7; ++t) {
                if ((mm[t] >> lane) & 1u) {
                    int rank = cum + part;
                    g_edgeRank[e + t] = rank;
                    g_edgeList[rank] = (v << 3) | (t + 1);
                    ++part;
                }
            }
        }
    } else {
        // ---- tet classify + chunk scan ----
        int ch = blockIdx.x - nRB;
        int base = ch*TCH + tid*SCAN_I;
        int R3 = R*R*R;
        unsigned loc[SCAN_I], sum = 0u;
#pragma unroll
        for (int it = 0; it < SCAN_I; ++it) {
            int r = base + it;
            unsigned add = 0u;
            if (r < T) {
                int p = r / R3, c = r - p*R3;
                unsigned code = g_cubeCode[c];
                int ti = ((code >> c_path[p][0]) & 1)
                       | (((code >> c_path[p][1]) & 1) << 1)
                       | (((code >> c_path[p][2]) & 1) << 2)
                       | (((code >> c_path[p][3]) & 1) << 3);
                int nt = c_ntri[ti];
                add = (nt == 1) ? 1u : ((nt == 2) ? 0x10000u : 0u);
            }
            loc[it] = sum; sum += add;
        }
        unsigned tot;
        unsigned exc = blk_exscan_u32<SCAN_B>(sum, tid, &tot);
#pragma unroll
        for (int it = 0; it < SCAN_I; ++it) {
            int r = base + it;
            if (r < T) g_tetScan[r] = exc + loc[it];
        }
        if (tid == SCAN_B-1) g_tBlkP[ch] = tot;
    }

    // last arriving block (rank or tet): exclusive scan of chunk sums
    if (last_block(&g_done2, gridDim.x)) {
        int K = (nCh + SCAN_B - 1) / SCAN_B;
        int b0 = tid * K;
        unsigned long long run = 0ull;
        for (int it = 0; it < K; ++it) {
            int idx = b0 + it;
            if (idx < nCh) {
                unsigned pkt = g_tBlkP[idx];
                run += (unsigned long long)(pkt & 0xffffu)
                     + ((unsigned long long)(pkt >> 16) << 32);
            }
        }
        unsigned long long tot64;
        unsigned long long exc64 = blk_exscan_u64<SCAN_B>(run, tid, &tot64);
        unsigned long long acc = exc64;
        for (int it = 0; it < K; ++it) {
            int idx = b0 + it;
            if (idx < nCh) {
                unsigned pkt = g_tBlkP[idx];
                g_tBlk64[idx] = acc;
                acc += (unsigned long long)(pkt & 0xffffu)
                     + ((unsigned long long)(pkt >> 16) << 32);
            }
        }
        if (tid == 0) g_n1 = (int)(tot64 & 0xffffffffull);
    }
}

// ---------------- kernel 4: fused emit (verts via list, faces via rank lookup) ----------------
__global__ void k_emit(const float* __restrict__ feats, float* __restrict__ out,
                       int E, int T, int R, int S, int rbR /* log2 R or -1 */)
{
    int idx = blockIdx.x*blockDim.x + threadIdx.x;
    int S2 = S*S;

    if (idx < E) {
        if (idx >= g_nv) return;
        int packed = g_edgeList[idx];
        int v = packed >> 3, t = packed & 7;
        int v2 = v + ((t>>2)&1)*S2 + ((t>>1)&1)*S + (t&1);
        float sa = g_sdf[v], sb = g_sdf[v2];
        float inv = 1.0f / (sa - sb);
        float wa = -sb * inv, wb = sa * inv;
        float* o = out + (size_t)idx * 6;
        o[0] = wa*g_rot[3*v+0] + wb*g_rot[3*v2+0];
        o[1] = wa*g_rot[3*v+1] + wb*g_rot[3*v2+1];
        o[2] = wa*g_rot[3*v+2] + wb*g_rot[3*v2+2];
        const float* fa = feats + (size_t)v  * 6 + 3;
        const float* fb = feats + (size_t)v2 * 6 + 3;
        o[3] = wa*fa[0] + wb*fb[0];
        o[4] = wa*fa[1] + wb*fb[1];
        o[5] = wa*fa[2] + wb*fb[2];
        return;
    }

    int r = idx - E;
    if (r >= T) return;
    int p, c, i, j, k;
    if (rbR >= 0) {
        p = r >> (3*rbR);  c = r & ((1 << (3*rbR)) - 1);
        i = c >> (2*rbR);  int rem = c & ((1 << (2*rbR)) - 1);
        j = rem >> rbR;    k = rem & (R - 1);
    } else {
        int R3 = R*R*R, R2 = R*R;
        p = r / R3; c = r - p*R3;
        i = c / R2; int rem = c - i*R2; j = rem / R; k = rem - j*R;
    }
    unsigned code = g_cubeCode[c];
    int P0 = c_path[p][0], P1 = c_path[p][1], P2 = c_path[p][2], P3 = c_path[p][3];
    int ti = ((code >> P0) & 1) | (((code >> P1) & 1) << 1)
           | (((code >> P2) & 1) << 2) | (((code >> P3) & 1) << 3);
    int nt = c_ntri[ti];
    if (!nt) return;

    int v000 = (i*S + j)*S + k;
    int PP[4] = {P0, P1, P2, P3};
    const int ea[6] = {0,0,0,1,1,2};
    const int eb[6] = {1,2,3,2,3,3};
    const int* tt = c_tri[ti];

    unsigned sc = g_tetScan[r];
    unsigned long long bk = g_tBlk64[r / TCH];
    size_t vbase = (size_t)g_nv * 6;

    if (nt == 1) {
        int s1 = (int)(sc & 0xffffu) + (int)(unsigned)(bk & 0xffffffffull);
        size_t o = vbase + (size_t)s1 * 3;
#pragma unroll
        for (int q = 0; q < 3; ++q) {
            int s = tt[q];
            int na = PP[ea[s]], nbn = PP[eb[s]];
            int va = v000 + ((na>>2)&1)*S2 + ((na>>1)&1)*S + (na&1);
            out[o+q] = (float)g_edgeRank[va*7 + (na ^ nbn) - 1];
        }
    } else {
        int s2 = (int)(sc >> 16) + (int)(unsigned)(bk >> 32);
        size_t o = vbase + ((size_t)g_n1 + 2*(size_t)s2) * 3;
#pragma unroll
        for (int q = 0; q < 6; ++q) {
            int s = tt[q];
            int na = PP[ea[s]], nbn = PP[eb[s]];
            int va = v000 + ((na>>2)&1)*S2 + ((na>>1)&1)*S + (na&1);
            out[o+q] = (float)g_edgeRank[va*7 + (na ^ nbn) - 1];
        }
    }
}

// ---------------- launch ----------------
extern "C" void kernel_launch(void* const* d_in, const int* in_sizes, int n_in,
                              void* d_out, int out_size)
{
    const float* feats  = (const float*)d_in[0];
    const float* sdf_n  = (const float*)d_in[1];
    const float* dir    = (const float*)d_in[2];
    const float* rotm   = (const float*)d_in[3];
    const float* scales = (const float*)d_in[4];

    int N = in_sizes[1];
    int S = 1;
    while ((long long)S*S*S < (long long)N) ++S;   // S = R+1
    int R = S - 1;
    int E = 7*N;
    int T = 6*R*R*R;
    int NC = R*R*R;
    int NG = (N + 31) >> 5;
    int nCh = (T + TCH - 1) / TCH;
    float dscale = 4.0f / (float)R;
    float* out = (float*)d_out;

    int rbR = -1;
    if ((R & (R-1)) == 0) { rbR = 0; while ((1 << rbR) < R) ++rbR; }

    int ngrp = (NC > NG) ? NC : NG;
    int nRB  = (NG + 7) / 8;          // rank blocks (8 warps = 8 groups per block)

    k_prep    <<<(N + 255)/256, 256>>>(sdf_n, dir, rotm, scales, N, dscale);
    k_grp     <<<(ngrp + 255)/256, 256>>>(N, S, NG, NC, R);
    k_rankscan<<<nRB + nCh, SCAN_B>>>(NG, nRB, T, R, nCh, S);
    k_emit    <<<(E + T + 255)/256, 256>>>(feats, out, E, T, R, S, rbR);
}

// round 11
// speedup vs baseline: 1.0863x; 1.0863x over previous
#include <cuda_runtime.h>
#include <math.h>

// ---------------- static scratch ----------------
#define SMAX   65
#define NMAXV  (SMAX*SMAX*SMAX)       // 274625 vertices
#define NWPAD  8832                   // occ bit-words + pad
#define NGMAX  9216                   // 32-anchor edge groups (padded)
#define NCMAX  (64*64*64)             // cubes
#define TMAXT  (6*NCMAX)              // tets
#define SCAN_B 256
#define SCAN_I 8
#define TCH    (SCAN_B*SCAN_I)        // 2048 tets per chunk
#define MAXCH  1024

__device__ unsigned           g_occw[NWPAD];
__device__ float4             g_va[NMAXV];        // (rot0, rot1, rot2, tanh_sdf)
__device__ float4             g_vb[NMAXV];        // (col0, col1, col2, 0)
__device__ uint4              g_egrp[NGMAX*2];    // 7 masks + exclusive base
__device__ int                g_eGrpCnt[NGMAX];
__device__ unsigned char      g_cubeCode[NCMAX];
__device__ int                g_edgeRank[7*NMAXV]; // TYPE-MAJOR: [t][v]
__device__ unsigned           g_tetScan[TMAXT];   // packed (cnt1 lo16 | cnt2 hi16)
__device__ unsigned           g_tBlkP[MAXCH];
__device__ unsigned long long g_tBlk64[MAXCH];
__device__ int                g_nv;
__device__ int                g_n1;
__device__ unsigned           g_done1;            // last-block counters (self-reset)
__device__ unsigned           g_done2;

__constant__ int c_path[6][4] = {
    {0,4,6,7},{0,4,5,7},{0,2,6,7},{0,2,3,7},{0,1,5,7},{0,1,3,7}};
__constant__ int c_ntri[16] = {0,1,1,2,1,2,2,1,1,2,2,1,2,1,1,0};
__constant__ int c_tri[16][6] = {
    {-1,-1,-1,-1,-1,-1},
    { 1, 0, 2,-1,-1,-1},
    { 4, 0, 3,-1,-1,-1},
    { 1, 4, 2, 1, 3, 4},
    { 3, 1, 5,-1,-1,-1},
    { 2, 3, 0, 2, 5, 3},
    { 1, 4, 0, 1, 5, 4},
    { 4, 2, 5,-1,-1,-1},
    { 4, 5, 2,-1,-1,-1},
    { 4, 1, 0, 4, 5, 1},
    { 3, 2, 0, 3, 5, 2},
    { 1, 3, 5,-1,-1,-1},
    { 4, 1, 2, 4, 3, 1},
    { 3, 0, 4,-1,-1,-1},
    { 2, 0, 1,-1,-1,-1},
    {-1,-1,-1,-1,-1,-1}};

__device__ __forceinline__ unsigned bits32(int b)
{
    unsigned w0 = g_occw[b >> 5];
    unsigned w1 = g_occw[(b >> 5) + 1];
    return __funnelshift_r(w0, w1, b & 31);
}

// shuffle-based exclusive block scan; ALL 32 lanes of warp 0 run the reduction
// shuffles (partial-warp shuffle with full mask hangs). Trailing sync: loop-safe.
template<int NT>
__device__ __forceinline__ unsigned blk_exscan_u32(unsigned v, int tid, unsigned* tot)
{
    constexpr int NW = NT/32;
    __shared__ unsigned ws[NW];
    int lane = tid & 31, w = tid >> 5;
    unsigned x = v;
#pragma unroll
    for (int o = 1; o < 32; o <<= 1) {
        unsigned y = __shfl_up_sync(0xffffffffu, x, o);
        if (lane >= o) x += y;
    }
    if (lane == 31) ws[w] = x;
    __syncthreads();
    if (w == 0) {
        unsigned t = (lane < NW) ? ws[lane] : 0u;
#pragma unroll
        for (int o = 1; o < NW; o <<= 1) {
            unsigned y = __shfl_up_sync(0xffffffffu, t, o);
            if (lane >= o) t += y;
        }
        if (lane < NW) ws[lane] = t;
    }
    __syncthreads();
    unsigned base = w ? ws[w-1] : 0u;
    *tot = ws[NW - 1];
    __syncthreads();
    return base + x - v;
}

template<int NT>
__device__ __forceinline__ unsigned long long blk_exscan_u64(unsigned long long v, int tid,
                                                             unsigned long long* tot)
{
    constexpr int NW = NT/32;
    __shared__ unsigned long long ws[NW];
    int lane = tid & 31, w = tid >> 5;
    unsigned long long x = v;
#pragma unroll
    for (int o = 1; o < 32; o <<= 1) {
        unsigned long long y = __shfl_up_sync(0xffffffffu, x, o);
        if (lane >= o) x += y;
    }
    if (lane == 31) ws[w] = x;
    __syncthreads();
    if (w == 0) {
        unsigned long long t = (lane < NW) ? ws[lane] : 0ull;
#pragma unroll
        for (int o = 1; o < NW; o <<= 1) {
            unsigned long long y = __shfl_up_sync(0xffffffffu, t, o);
            if (lane >= o) t += y;
        }
        if (lane < NW) ws[lane] = t;
    }
    __syncthreads();
    unsigned long long base = w ? ws[w-1] : 0ull;
    *tot = ws[NW - 1];
    __syncthreads();
    return base + x - v;
}

// last-block-done: returns true in exactly one block after all blocks arrive.
__device__ __forceinline__ bool last_block(unsigned* ctr, unsigned nb)
{
    __shared__ unsigned s_last;
    __threadfence();
    __syncthreads();
    if (threadIdx.x == 0) {
        unsigned prev = atomicAdd(ctr, 1u);
        if (prev == nb - 1u) { *ctr = 0u; s_last = 1u; }   // self-reset for replay
        else                 s_last = 0u;
    }
    __syncthreads();
    return s_last != 0u;
}

// ---------------- kernel 1: per-vertex prep + occ bit-pack + float4 packs ----------------
__global__ void k_prep(const float* __restrict__ feats,
                       const float* __restrict__ sdf_n,
                       const float* __restrict__ dir,
                       const float* __restrict__ rotm,
                       const float* __restrict__ scales,
                       int N, float dscale)
{
    int v = blockIdx.x*blockDim.x + threadIdx.x;
    bool inb = v < N;
    float s = inb ? sdf_n[v] : -1.0f;
    unsigned bal = __ballot_sync(0xffffffffu, s > 0.0f);
    if ((threadIdx.x & 31) == 0) g_occw[v >> 5] = bal;
    if (!inb) return;

    float ts = tanhf(s);
    float l0 = dscale * tanhf(dir[2*v+0]);
    float l1 = dscale * tanhf(dir[2*v+1]);
    const float* m = rotm + 9*(size_t)v;
    float sc = scales[v];
    g_va[v] = make_float4((m[0]*l0 + m[3]*l1 + m[6]) * sc,
                          (m[1]*l0 + m[4]*l1 + m[7]) * sc,
                          (m[2]*l0 + m[5]*l1 + m[8]) * sc, ts);
    const float* f = feats + (size_t)v * 6;
    g_vb[v] = make_float4(f[3], f[4], f[5], 0.0f);
}

// ---------------- kernel 2: masks + counts + cube codes; last block scans ----------------
__global__ void k_grp(int N, int S, int NG, int NC, int R)
{
    int t = blockIdx.x*blockDim.x + threadIdx.x;
    int S2 = S*S;

    if (t < NG) {
        int v0 = t << 5;
        int i0 = v0 / S2; int rem = v0 - i0*S2; int j0 = rem / S; int k0 = rem - j0*S;
        int qw = S - k0;
        unsigned pre = (qw >= 32) ? 0xffffffffu : ((1u << (qw & 31)) - 1u);
        int j1 = j0 + 1, i1 = i0; if (j1 == S) { j1 = 0; ++i1; }
        int nvld = N - v0;
        unsigned tailm = (nvld >= 32) ? 0xffffffffu : ((1u << (nvld & 31)) - 1u);
        unsigned A = bits32(v0);
        unsigned mm[7]; int cnt = 0;
#pragma unroll
        for (int tt = 1; tt <= 7; ++tt) {
            int di = (tt>>2)&1, dj = (tt>>1)&1, dk = tt&1;
            int d = di*S2 + dj*S + dk;
            unsigned X = A ^ bits32(v0 + d);
            unsigned vm = (((i0+di < S) && (j0+dj < S)) ? pre : 0u)
                        | (((i1+di < S) && (j1+dj < S)) ? ~pre : 0u);
            if (dk && (qw - 1) < 32) vm &= ~(1u << (qw - 1));
            vm &= tailm;
            mm[tt-1] = X & vm;
            cnt += __popc(mm[tt-1]);
        }
        g_egrp[2*t]   = make_uint4(mm[0], mm[1], mm[2], mm[3]);
        g_egrp[2*t+1] = make_uint4(mm[4], mm[5], mm[6], 0u);
        g_eGrpCnt[t]  = cnt;
    }

    if (t < NC) {
        int R2 = R*R;
        int i = t / R2; int rem = t - i*R2; int j = rem / R; int k = rem - j*R;
        int b = (i*S + j)*S + k;
        unsigned p00 = bits32(b)          & 3u;
        unsigned p01 = bits32(b + S)      & 3u;
        unsigned p10 = bits32(b + S2)     & 3u;
        unsigned p11 = bits32(b + S2 + S) & 3u;
        g_cubeCode[t] = (unsigned char)(p00 | (p01 << 2) | (p10 << 4) | (p11 << 6));
    }

    // last arriving block: exclusive scan over group counts (L2-hot)
    if (last_block(&g_done1, gridDim.x)) {
        int tid = threadIdx.x;
        int K = (NG + SCAN_B - 1) / SCAN_B;
        int base = tid * K;
        int run = 0;
        for (int it = 0; it < K; ++it) {
            int idx = base + it;
            if (idx < NG) run += g_eGrpCnt[idx];
        }
        unsigned tot;
        unsigned exc = blk_exscan_u32<SCAN_B>((unsigned)run, tid, &tot);
        int acc = (int)exc;
        for (int it = 0; it < K; ++it) {
            int idx = base + it;
            if (idx < NG) {
                int c = g_eGrpCnt[idx];
                ((unsigned*)g_egrp)[idx*8 + 7] = (unsigned)acc;
                acc += c;
            }
        }
        if (tid == 0) g_nv = (int)tot;
    }
}

// ---------------- kernel 3: rank + VERTEX EMIT (warp/group) + tet scan ----------------
__global__ void k_rankscan(float* __restrict__ out,
                           int NG, int nRB, int T, int R, int nCh, int S)
{
    int tid = threadIdx.x;

    if (blockIdx.x < nRB) {
        // ---- one warp per 32-anchor group: compute ranks, emit vertices ----
        int g = blockIdx.x*8 + (tid >> 5);
        if (g < NG) {
            int lane = tid & 31;
            uint4 Aa = g_egrp[2*g], Bb = g_egrp[2*g+1];
            unsigned mm[7] = {Aa.x, Aa.y, Aa.z, Aa.w, Bb.x, Bb.y, Bb.z};
            unsigned low = (1u << lane) - 1u;
            int cum = (int)Bb.w;
#pragma unroll
            for (int x = 0; x < 7; ++x) cum += __popc(mm[x] & low);
            int v = (g << 5) + lane;
            int S2 = S*S;
            // hoisted endpoint-a data (only if any edge crossing)
            unsigned any = 0u;
#pragma unroll
            for (int x = 0; x < 7; ++x) any |= (mm[x] >> lane) & 1u;
            if (any) {
                float4 A = g_va[v];
                float4 B = g_vb[v];
                int part = 0;
#pragma unroll
                for (int t = 0; t < 7; ++t) {
                    if ((mm[t] >> lane) & 1u) {
                        int rank = cum + part; ++part;
                        g_edgeRank[t*NMAXV + v] = rank;
                        int type = t + 1;
                        int v2 = v + ((type>>2)&1)*S2 + ((type>>1)&1)*S + (type&1);
                        float4 A2 = g_va[v2];
                        float4 B2 = g_vb[v2];
                        float inv = 1.0f / (A.w - A2.w);
                        float wa = -A2.w * inv, wb = A.w * inv;
                        float2* o = (float2*)(out + (size_t)rank * 6);
                        o[0] = make_float2(wa*A.x + wb*A2.x, wa*A.y + wb*A2.y);
                        o[1] = make_float2(wa*A.z + wb*A2.z, wa*B.x + wb*B2.x);
                        o[2] = make_float2(wa*B.y + wb*B2.y, wa*B.z + wb*B2.z);
                    }
                }
            }
        }
    } else {
        // ---- tet classify + chunk scan ----
        int ch = blockIdx.x - nRB;
        int base = ch*TCH + tid*SCAN_I;
        int R3 = R*R*R;
        unsigned loc[SCAN_I], sum = 0u;
#pragma unroll
        for (int it = 0; it < SCAN_I; ++it) {
            int r = base + it;
            unsigned add = 0u;
            if (r < T) {
                int p = r / R3, c = r - p*R3;
                unsigned code = g_cubeCode[c];
                int ti = ((code >> c_path[p][0]) & 1)
                       | (((code >> c_path[p][1]) & 1) << 1)
                       | (((code >> c_path[p][2]) & 1) << 2)
                       | (((code >> c_path[p][3]) & 1) << 3);
                int nt = c_ntri[ti];
                add = (nt == 1) ? 1u : ((nt == 2) ? 0x10000u : 0u);
            }
            loc[it] = sum; sum += add;
        }
        unsigned tot;
        unsigned exc = blk_exscan_u32<SCAN_B>(sum, tid, &tot);
#pragma unroll
        for (int it = 0; it < SCAN_I; ++it) {
            int r = base + it;
            if (r < T) g_tetScan[r] = exc + loc[it];
        }
        if (tid == SCAN_B-1) g_tBlkP[ch] = tot;
    }

    // last arriving block: exclusive scan of chunk sums
    if (last_block(&g_done2, gridDim.x)) {
        int K = (nCh + SCAN_B - 1) / SCAN_B;
        int b0 = tid * K;
        unsigned long long run = 0ull;
        for (int it = 0; it < K; ++it) {
            int idx = b0 + it;
            if (idx < nCh) {
                unsigned pkt = g_tBlkP[idx];
                run += (unsigned long long)(pkt & 0xffffu)
                     + ((unsigned long long)(pkt >> 16) << 32);
            }
        }
        unsigned long long tot64;
        unsigned long long exc64 = blk_exscan_u64<SCAN_B>(run, tid, &tot64);
        unsigned long long acc = exc64;
        for (int it = 0; it < K; ++it) {
            int idx = b0 + it;
            if (idx < nCh) {
                unsigned pkt = g_tBlkP[idx];
                g_tBlk64[idx] = acc;
                acc += (unsigned long long)(pkt & 0xffffu)
                     + ((unsigned long long)(pkt >> 16) << 32);
            }
        }
        if (tid == 0) g_n1 = (int)(tot64 & 0xffffffffull);
    }
}

// ---------------- kernel 4: faces only (coalesced type-major rank lookups) ----------------
__global__ void k_faces(float* __restrict__ out,
                        int T, int R, int S, int rbR /* log2 R or -1 */)
{
    int r = blockIdx.x*blockDim.x + threadIdx.x;
    if (r >= T) return;
    int S2 = S*S;
    int p, c, i, j, k;
    if (rbR >= 0) {
        p = r >> (3*rbR);  c = r & ((1 << (3*rbR)) - 1);
        i = c >> (2*rbR);  int rem = c & ((1 << (2*rbR)) - 1);
        j = rem >> rbR;    k = rem & (R - 1);
    } else {
        int R3 = R*R*R, R2 = R*R;
        p = r / R3; c = r - p*R3;
        i = c / R2; int rem = c - i*R2; j = rem / R; k = rem - j*R;
    }
    unsigned code = g_cubeCode[c];
    int P0 = c_path[p][0], P1 = c_path[p][1], P2 = c_path[p][2], P3 = c_path[p][3];
    int ti = ((code >> P0) & 1) | (((code >> P1) & 1) << 1)
           | (((code >> P2) & 1) << 2) | (((code >> P3) & 1) << 3);
    int nt = c_ntri[ti];
    if (!nt) return;

    int v000 = (i*S + j)*S + k;
    int PP[4] = {P0, P1, P2, P3};
    const int ea[6] = {0,0,0,1,1,2};
    const int eb[6] = {1,2,3,2,3,3};
    const int* tt = c_tri[ti];

    unsigned sc = g_tetScan[r];
    unsigned long long bk = g_tBlk64[r / TCH];
    size_t vbase = (size_t)g_nv * 6;

    if (nt == 1) {
        int s1 = (int)(sc & 0xffffu) + (int)(unsigned)(bk & 0xffffffffull);
        size_t o = vbase + (size_t)s1 * 3;
#pragma unroll
        for (int q = 0; q < 3; ++q) {
            int s = tt[q];
            int na = PP[ea[s]], nbn = PP[eb[s]];
            int va = v000 + ((na>>2)&1)*S2 + ((na>>1)&1)*S + (na&1);
            out[o+q] = (float)g_edgeRank[((na ^ nbn) - 1)*NMAXV + va];
        }
    } else {
        int s2 = (int)(sc >> 16) + (int)(unsigned)(bk >> 32);
        size_t o = vbase + ((size_t)g_n1 + 2*(size_t)s2) * 3;
#pragma unroll
        for (int q = 0; q < 6; ++q) {
            int s = tt[q];
            int na = PP[ea[s]], nbn = PP[eb[s]];
            int va = v000 + ((na>>2)&1)*S2 + ((na>>1)&1)*S + (na&1);
            out[o+q] = (float)g_edgeRank[((na ^ nbn) - 1)*NMAXV + va];
        }
    }
}

// ---------------- launch ----------------
extern "C" void kernel_launch(void* const* d_in, const int* in_sizes, int n_in,
                              void* d_out, int out_size)
{
    const float* feats  = (const float*)d_in[0];
    const float* sdf_n  = (const float*)d_in[1];
    const float* dir    = (const float*)d_in[2];
    const float* rotm   = (const float*)d_in[3];
    const float* scales = (const float*)d_in[4];

    int N = in_sizes[1];
    int S = 1;
    while ((long long)S*S*S < (long long)N) ++S;   // S = R+1
    int R = S - 1;
    int T = 6*R*R*R;
    int NC = R*R*R;
    int NG = (N + 31) >> 5;
    int nCh = (T + TCH - 1) / TCH;
    float dscale = 4.0f / (float)R;
    float* out = (float*)d_out;

    int rbR = -1;
    if ((R & (R-1)) == 0) { rbR = 0; while ((1 << rbR) < R) ++rbR; }

    int ngrp = (NC > NG) ? NC : NG;
    int nRB  = (NG + 7) / 8;          // rank blocks (8 warps = 8 groups per block)

    k_prep    <<<(N + 255)/256, 256>>>(feats, sdf_n, dir, rotm, scales, N, dscale);
    k_grp     <<<(ngrp + 255)/256, 256>>>(N, S, NG, NC, R);
    k_rankscan<<<nRB + nCh, SCAN_B>>>(out, NG, nRB, T, R, nCh, S);
    k_faces   <<<(T + 255)/256, 256>>>(out, T, R, S, rbR);
}

// round 12
// speedup vs baseline: 1.2321x; 1.1342x over previous
#include <cuda_runtime.h>
#include <math.h>

// ---------------- static scratch ----------------
#define SMAX   65
#define NMAXV  (SMAX*SMAX*SMAX)       // 274625 vertices
#define NWPAD  8832                   // occ bit-words + pad
#define NGMAX  9216                   // 32-anchor edge groups (padded)
#define NCMAX  (64*64*64)             // cubes
#define TMAXT  (6*NCMAX)              // tets
#define SCAN_B 256
#define SCAN_I 8
#define TCH    (SCAN_B*SCAN_I)        // 2048 tets per chunk
#define MAXCH  1024

__device__ unsigned           g_occw[NWPAD];
__device__ float4             g_va[NMAXV];        // (rot0, rot1, rot2, tanh_sdf)
__device__ float4             g_vb[NMAXV];        // (col0, col1, col2, 0)
__device__ uint4              g_egrp[NGMAX*2];    // 7 masks + exclusive base
__device__ int                g_eGrpCnt[NGMAX];
__device__ unsigned char      g_cubeCode[NCMAX];
__device__ int                g_edgeRank[7*NMAXV]; // TYPE-MAJOR: [t][v]
__device__ int                g_edgeList[7*NMAXV]; // packed (v<<3)|type per rank
__device__ unsigned           g_tetScan[TMAXT];   // packed (cnt1 lo16 | cnt2 hi16)
__device__ unsigned           g_tBlkP[MAXCH];
__device__ unsigned long long g_tBlk64[MAXCH];
__device__ int                g_nv;
__device__ int                g_n1;
__device__ unsigned           g_done1;            // last-block counters (self-reset)
__device__ unsigned           g_done2;

__constant__ int c_path[6][4] = {
    {0,4,6,7},{0,4,5,7},{0,2,6,7},{0,2,3,7},{0,1,5,7},{0,1,3,7}};
__constant__ int c_ntri[16] = {0,1,1,2,1,2,2,1,1,2,2,1,2,1,1,0};
__constant__ int c_tri[16][6] = {
    {-1,-1,-1,-1,-1,-1},
    { 1, 0, 2,-1,-1,-1},
    { 4, 0, 3,-1,-1,-1},
    { 1, 4, 2, 1, 3, 4},
    { 3, 1, 5,-1,-1,-1},
    { 2, 3, 0, 2, 5, 3},
    { 1, 4, 0, 1, 5, 4},
    { 4, 2, 5,-1,-1,-1},
    { 4, 5, 2,-1,-1,-1},
    { 4, 1, 0, 4, 5, 1},
    { 3, 2, 0, 3, 5, 2},
    { 1, 3, 5,-1,-1,-1},
    { 4, 1, 2, 4, 3, 1},
    { 3, 0, 4,-1,-1,-1},
    { 2, 0, 1,-1,-1,-1},
    {-1,-1,-1,-1,-1,-1}};

__device__ __forceinline__ unsigned bits32(int b)
{
    unsigned w0 = g_occw[b >> 5];
    unsigned w1 = g_occw[(b >> 5) + 1];
    return __funnelshift_r(w0, w1, b & 31);
}

// shuffle-based exclusive block scan; ALL 32 lanes of warp 0 run the reduction
// shuffles (partial-warp shuffle with full mask hangs). Trailing sync: loop-safe.
template<int NT>
__device__ __forceinline__ unsigned blk_exscan_u32(unsigned v, int tid, unsigned* tot)
{
    constexpr int NW = NT/32;
    __shared__ unsigned ws[NW];
    int lane = tid & 31, w = tid >> 5;
    unsigned x = v;
#pragma unroll
    for (int o = 1; o < 32; o <<= 1) {
        unsigned y = __shfl_up_sync(0xffffffffu, x, o);
        if (lane >= o) x += y;
    }
    if (lane == 31) ws[w] = x;
    __syncthreads();
    if (w == 0) {
        unsigned t = (lane < NW) ? ws[lane] : 0u;
#pragma unroll
        for (int o = 1; o < NW; o <<= 1) {
            unsigned y = __shfl_up_sync(0xffffffffu, t, o);
            if (lane >= o) t += y;
        }
        if (lane < NW) ws[lane] = t;
    }
    __syncthreads();
    unsigned base = w ? ws[w-1] : 0u;
    *tot = ws[NW - 1];
    __syncthreads();
    return base + x - v;
}

template<int NT>
__device__ __forceinline__ unsigned long long blk_exscan_u64(unsigned long long v, int tid,
                                                             unsigned long long* tot)
{
    constexpr int NW = NT/32;
    __shared__ unsigned long long ws[NW];
    int lane = tid & 31, w = tid >> 5;
    unsigned long long x = v;
#pragma unroll
    for (int o = 1; o < 32; o <<= 1) {
        unsigned long long y = __shfl_up_sync(0xffffffffu, x, o);
        if (lane >= o) x += y;
    }
    if (lane == 31) ws[w] = x;
    __syncthreads();
    if (w == 0) {
        unsigned long long t = (lane < NW) ? ws[lane] : 0ull;
#pragma unroll
        for (int o = 1; o < NW; o <<= 1) {
            unsigned long long y = __shfl_up_sync(0xffffffffu, t, o);
            if (lane >= o) t += y;
        }
        if (lane < NW) ws[lane] = t;
    }
    __syncthreads();
    unsigned long long base = w ? ws[w-1] : 0ull;
    *tot = ws[NW - 1];
    __syncthreads();
    return base + x - v;
}

// last-block-done: returns true in exactly one block after all blocks arrive.
__device__ __forceinline__ bool last_block(unsigned* ctr, unsigned nb)
{
    __shared__ unsigned s_last;
    __threadfence();
    __syncthreads();
    if (threadIdx.x == 0) {
        unsigned prev = atomicAdd(ctr, 1u);
        if (prev == nb - 1u) { *ctr = 0u; s_last = 1u; }   // self-reset for replay
        else                 s_last = 0u;
    }
    __syncthreads();
    return s_last != 0u;
}

// ---------------- kernel 1: per-vertex prep + occ bit-pack + float4 packs ----------------
__global__ void k_prep(const float* __restrict__ feats,
                       const float* __restrict__ sdf_n,
                       const float* __restrict__ dir,
                       const float* __restrict__ rotm,
                       const float* __restrict__ scales,
                       int N, float dscale)
{
    int v = blockIdx.x*blockDim.x + threadIdx.x;
    bool inb = v < N;
    float s = inb ? sdf_n[v] : -1.0f;
    unsigned bal = __ballot_sync(0xffffffffu, s > 0.0f);
    if ((threadIdx.x & 31) == 0) g_occw[v >> 5] = bal;
    if (!inb) return;

    float ts = tanhf(s);
    float l0 = dscale * tanhf(dir[2*v+0]);
    float l1 = dscale * tanhf(dir[2*v+1]);
    const float* m = rotm + 9*(size_t)v;
    float sc = scales[v];
    g_va[v] = make_float4((m[0]*l0 + m[3]*l1 + m[6]) * sc,
                          (m[1]*l0 + m[4]*l1 + m[7]) * sc,
                          (m[2]*l0 + m[5]*l1 + m[8]) * sc, ts);
    const float* f = feats + (size_t)v * 6;
    g_vb[v] = make_float4(f[3], f[4], f[5], 0.0f);
}

// ---------------- kernel 2: masks + counts + cube codes; last block scans ----------------
__global__ void k_grp(int N, int S, int NG, int NC, int R)
{
    int t = blockIdx.x*blockDim.x + threadIdx.x;
    int S2 = S*S;

    if (t < NG) {
        int v0 = t << 5;
        int i0 = v0 / S2; int rem = v0 - i0*S2; int j0 = rem / S; int k0 = rem - j0*S;
        int qw = S - k0;
        unsigned pre = (qw >= 32) ? 0xffffffffu : ((1u << (qw & 31)) - 1u);
        int j1 = j0 + 1, i1 = i0; if (j1 == S) { j1 = 0; ++i1; }
        int nvld = N - v0;
        unsigned tailm = (nvld >= 32) ? 0xffffffffu : ((1u << (nvld & 31)) - 1u);
        unsigned A = bits32(v0);
        unsigned mm[7]; int cnt = 0;
#pragma unroll
        for (int tt = 1; tt <= 7; ++tt) {
            int di = (tt>>2)&1, dj = (tt>>1)&1, dk = tt&1;
            int d = di*S2 + dj*S + dk;
            unsigned X = A ^ bits32(v0 + d);
            unsigned vm = (((i0+di < S) && (j0+dj < S)) ? pre : 0u)
                        | (((i1+di < S) && (j1+dj < S)) ? ~pre : 0u);
            if (dk && (qw - 1) < 32) vm &= ~(1u << (qw - 1));
            vm &= tailm;
            mm[tt-1] = X & vm;
            cnt += __popc(mm[tt-1]);
        }
        g_egrp[2*t]   = make_uint4(mm[0], mm[1], mm[2], mm[3]);
        g_egrp[2*t+1] = make_uint4(mm[4], mm[5], mm[6], 0u);
        g_eGrpCnt[t]  = cnt;
    }

    if (t < NC) {
        int R2 = R*R;
        int i = t / R2; int rem = t - i*R2; int j = rem / R; int k = rem - j*R;
        int b = (i*S + j)*S + k;
        unsigned p00 = bits32(b)          & 3u;
        unsigned p01 = bits32(b + S)      & 3u;
        unsigned p10 = bits32(b + S2)     & 3u;
        unsigned p11 = bits32(b + S2 + S) & 3u;
        g_cubeCode[t] = (unsigned char)(p00 | (p01 << 2) | (p10 << 4) | (p11 << 6));
    }

    // last arriving block: exclusive scan over group counts (L2-hot)
    if (last_block(&g_done1, gridDim.x)) {
        int tid = threadIdx.x;
        int K = (NG + SCAN_B - 1) / SCAN_B;
        int base = tid * K;
        int run = 0;
        for (int it = 0; it < K; ++it) {
            int idx = base + it;
            if (idx < NG) run += g_eGrpCnt[idx];
        }
        unsigned tot;
        unsigned exc = blk_exscan_u32<SCAN_B>((unsigned)run, tid, &tot);
        int acc = (int)exc;
        for (int it = 0; it < K; ++it) {
            int idx = base + it;
            if (idx < NG) {
                int c = g_eGrpCnt[idx];
                ((unsigned*)g_egrp)[idx*8 + 7] = (unsigned)acc;
                acc += c;
            }
        }
        if (tid == 0) g_nv = (int)tot;
    }
}

// ---------------- kernel 3: rank table + edge list (warp/group) + tet scan ----------------
__global__ void k_rankscan(int NG, int nRB, int T, int R, int nCh, int S)
{
    int tid = threadIdx.x;

    if (blockIdx.x < nRB) {
        // ---- one warp per 32-anchor group: compute ranks ----
        int g = blockIdx.x*8 + (tid >> 5);
        if (g < NG) {
            int lane = tid & 31;
            uint4 Aa = g_egrp[2*g], Bb = g_egrp[2*g+1];
            unsigned mm[7] = {Aa.x, Aa.y, Aa.z, Aa.w, Bb.x, Bb.y, Bb.z};
            unsigned low = (1u << lane) - 1u;
            int cum = (int)Bb.w;
#pragma unroll
            for (int x = 0; x < 7; ++x) cum += __popc(mm[x] & low);
            int v = (g << 5) + lane;
            int part = 0;
#pragma unroll
            for (int t = 0; t < 7; ++t) {
                if ((mm[t] >> lane) & 1u) {
                    int rank = cum + part; ++part;
                    g_edgeRank[t*NMAXV + v] = rank;
                    g_edgeList[rank] = (v << 3) | (t + 1);
                }
            }
        }
    } else {
        // ---- tet classify + chunk scan ----
        int ch = blockIdx.x - nRB;
        int base = ch*TCH + tid*SCAN_I;
        int R3 = R*R*R;
        unsigned loc[SCAN_I], sum = 0u;
#pragma unroll
        for (int it = 0; it < SCAN_I; ++it) {
            int r = base + it;
            unsigned add = 0u;
            if (r < T) {
                int p = r / R3, c = r - p*R3;
                unsigned code = g_cubeCode[c];
                int ti = ((code >> c_path[p][0]) & 1)
                       | (((code >> c_path[p][1]) & 1) << 1)
                       | (((code >> c_path[p][2]) & 1) << 2)
                       | (((code >> c_path[p][3]) & 1) << 3);
                int nt = c_ntri[ti];
                add = (nt == 1) ? 1u : ((nt == 2) ? 0x10000u : 0u);
            }
            loc[it] = sum; sum += add;
        }
        unsigned tot;
        unsigned exc = blk_exscan_u32<SCAN_B>(sum, tid, &tot);
#pragma unroll
        for (int it = 0; it < SCAN_I; ++it) {
            int r = base + it;
            if (r < T) g_tetScan[r] = exc + loc[it];
        }
        if (tid == SCAN_B-1) g_tBlkP[ch] = tot;
    }

    // last arriving block: exclusive scan of chunk sums
    if (last_block(&g_done2, gridDim.x)) {
        int K = (nCh + SCAN_B - 1) / SCAN_B;
        int b0 = tid * K;
        unsigned long long run = 0ull;
        for (int it = 0; it < K; ++it) {
            int idx = b0 + it;
            if (idx < nCh) {
                unsigned pkt = g_tBlkP[idx];
                run += (unsigned long long)(pkt & 0xffffu)
                     + ((unsigned long long)(pkt >> 16) << 32);
            }
        }
        unsigned long long tot64;
        unsigned long long exc64 = blk_exscan_u64<SCAN_B>(run, tid, &tot64);
        unsigned long long acc = exc64;
        for (int it = 0; it < K; ++it) {
            int idx = b0 + it;
            if (idx < nCh) {
                unsigned pkt = g_tBlkP[idx];
                g_tBlk64[idx] = acc;
                acc += (unsigned long long)(pkt & 0xffffu)
                     + ((unsigned long long)(pkt >> 16) << 32);
            }
        }
        if (tid == 0) g_n1 = (int)(tot64 & 0xffffffffull);
    }
}

// ---------------- kernel 4: fused emit — verts (rank-dense) + faces ----------------
__global__ void k_emit(float* __restrict__ out,
                       int nVB, int T, int R, int S, int rbR /* log2 R or -1 */)
{
    int tid = threadIdx.x;
    int S2 = S*S;

    if (blockIdx.x < nVB) {
        // ===== vertex emit: thread-per-output-vertex, smem-staged dense stores =====
        __shared__ float sm[SCAN_B * 6];
        int nv = g_nv;
        int b0 = blockIdx.x * SCAN_B;
        if (b0 >= nv) return;
        int cnt = nv - b0; if (cnt > SCAN_B) cnt = SCAN_B;
        int idx = b0 + tid;
        if (tid < cnt) {
            int packed = g_edgeList[idx];
            int v = packed >> 3, t = packed & 7;
            int v2 = v + ((t>>2)&1)*S2 + ((t>>1)&1)*S + (t&1);
            float4 A  = g_va[v];
            float4 A2 = g_va[v2];
            float4 B  = g_vb[v];
            float4 B2 = g_vb[v2];
            float inv = 1.0f / (A.w - A2.w);
            float wa = -A2.w * inv, wb = A.w * inv;
            float* o = sm + tid*6;
            o[0] = wa*A.x + wb*A2.x;
            o[1] = wa*A.y + wb*A2.y;
            o[2] = wa*A.z + wb*A2.z;
            o[3] = wa*B.x + wb*B2.x;
            o[4] = wa*B.y + wb*B2.y;
            o[5] = wa*B.z + wb*B2.z;
        }
        __syncthreads();
        // dense coalesced write of the block's contiguous span
        float2* dst = (float2*)(out + (size_t)b0 * 6);
        const float2* src = (const float2*)sm;
        int nf2 = 3 * cnt;
        for (int i = tid; i < nf2; i += SCAN_B) dst[i] = src[i];
        return;
    }

    // ===== faces: warp-uniform edge types -> coalesced rank loads =====
    int r = (blockIdx.x - nVB)*SCAN_B + tid;
    if (r >= T) return;
    int p, c, i, j, k;
    if (rbR >= 0) {
        p = r >> (3*rbR);  c = r & ((1 << (3*rbR)) - 1);
        i = c >> (2*rbR);  int rem = c & ((1 << (2*rbR)) - 1);
        j = rem >> rbR;    k = rem & (R - 1);
    } else {
        int R3 = R*R*R, R2 = R*R;
        p = r / R3; c = r - p*R3;
        i = c / R2; int rem = c - i*R2; j = rem / R; k = rem - j*R;
    }
    unsigned code = g_cubeCode[c];
    int P0 = c_path[p][0], P1 = c_path[p][1], P2 = c_path[p][2], P3 = c_path[p][3];
    int ti = ((code >> P0) & 1) | (((code >> P1) & 1) << 1)
           | (((code >> P2) & 1) << 2) | (((code >> P3) & 1) << 3);
    int nt = c_ntri[ti];
    if (!nt) return;

    int v000 = (i*S + j)*S + k;
    int PP[4] = {P0, P1, P2, P3};
    const int ea[6] = {0,0,0,1,1,2};
    const int eb[6] = {1,2,3,2,3,3};

    // Load ALL 6 edge ranks: slot s has warp-uniform type (same p across warp)
    // and consecutive va across lanes -> fully coalesced.
    int er[6];
#pragma unroll
    for (int s = 0; s < 6; ++s) {
        int na = PP[ea[s]], nbn = PP[eb[s]];
        int va = v000 + ((na>>2)&1)*S2 + ((na>>1)&1)*S + (na&1);
        er[s] = g_edgeRank[((na ^ nbn) - 1)*NMAXV + va];
    }

    unsigned sc = g_tetScan[r];
    unsigned long long bk = g_tBlk64[r / TCH];
    size_t vbase = (size_t)g_nv * 6;
    const int* tt = c_tri[ti];

    if (nt == 1) {
        int s1 = (int)(sc & 0xffffu) + (int)(unsigned)(bk & 0xffffffffull);
        size_t o = vbase + (size_t)s1 * 3;
        out[o+0] = (float)er[tt[0]];
        out[o+1] = (float)er[tt[1]];
        out[o+2] = (float)er[tt[2]];
    } else {
        int s2 = (int)(sc >> 16) + (int)(unsigned)(bk >> 32);
        size_t o = vbase + ((size_t)g_n1 + 2*(size_t)s2) * 3;
#pragma unroll
        for (int q = 0; q < 6; ++q)
            out[o+q] = (float)er[tt[q]];
    }
}

// ---------------- launch ----------------
extern "C" void kernel_launch(void* const* d_in, const int* in_sizes, int n_in,
                              void* d_out, int out_size)
{
    const float* feats  = (const float*)d_in[0];
    const float* sdf_n  = (const float*)d_in[1];
    const float* dir    = (const float*)d_in[2];
    const float* rotm   = (const float*)d_in[3];
    const float* scales = (const float*)d_in[4];

    int N = in_sizes[1];
    int S = 1;
    while ((long long)S*S*S < (long long)N) ++S;   // S = R+1
    int R = S - 1;
    int E = 7*N;
    int T = 6*R*R*R;
    int NC = R*R*R;
    int NG = (N + 31) >> 5;
    int nCh = (T + TCH - 1) / TCH;
    float dscale = 4.0f / (float)R;
    float* out = (float*)d_out;

    int rbR = -1;
    if ((R & (R-1)) == 0) { rbR = 0; while ((1 << rbR) < R) ++rbR; }

    int ngrp = (NC > NG) ? NC : NG;
    int nRB  = (NG + 7) / 8;              // rank blocks (8 warps = 8 groups per block)
    int nVB  = (E + SCAN_B - 1) / SCAN_B; // vertex-emit blocks (covers worst-case nv)
    int nFB  = (T + SCAN_B - 1) / SCAN_B; // face blocks

    k_prep    <<<(N + 255)/256, 256>>>(feats, sdf_n, dir, rotm, scales, N, dscale);
    k_grp     <<<(ngrp + 255)/256, 256>>>(N, S, NG, NC, R);
    k_rankscan<<<nRB + nCh, SCAN_B>>>(NG, nRB, T, R, nCh, S);
    k_emit    <<<nVB + nFB, SCAN_B>>>(out, nVB, T, R, S, rbR);
}

// round 13
// speedup vs baseline: 1.4216x; 1.1538x over previous
#include <cuda_runtime.h>
#include <math.h>

// ---------------- static scratch ----------------
#define SMAX   65
#define NMAXV  (SMAX*SMAX*SMAX)       // 274625 vertices
#define NWPAD  8832                   // occ bit-words + pad
#define NGMAX  9216                   // 32-anchor edge groups (padded)
#define NCMAX  (64*64*64)             // cubes
#define TMAXT  (6*NCMAX)              // tets
#define SCAN_B 256
#define SCAN_I 8
#define TCH    (SCAN_B*SCAN_I)        // 2048 tets per chunk
#define MAXCH  1024
#define NT_PACK 0x16696994u           // 2-bit ntri LUT (verified vs c_ntri)

__device__ unsigned           g_occw[NWPAD];
__device__ float4             g_va[NMAXV];        // (rot0, rot1, rot2, tanh_sdf)
__device__ float4             g_vb[NMAXV];        // (col0, col1, col2, 0)
__device__ uint4              g_egrp[NGMAX*2];    // 7 masks + exclusive base
__device__ int                g_eGrpCnt[NGMAX];
__device__ unsigned char      g_cubeCode[NCMAX];
__device__ int                g_edgeRank[7*NMAXV]; // TYPE-MAJOR: [t][v]
__device__ int                g_edgeList[7*NMAXV]; // packed (v<<3)|type per rank
__device__ unsigned           g_tetScan[TMAXT];   // packed (cnt1 lo16 | cnt2 hi16)
__device__ unsigned           g_tBlkP[MAXCH];
__device__ unsigned long long g_tBlk64[MAXCH];
__device__ int                g_nv;
__device__ int                g_n1;
__device__ unsigned           g_done1;            // last-block counters (self-reset)
__device__ unsigned           g_done2;

__constant__ int c_path[6][4] = {
    {0,4,6,7},{0,4,5,7},{0,2,6,7},{0,2,3,7},{0,1,5,7},{0,1,3,7}};
__constant__ int c_tri[16][6] = {
    {-1,-1,-1,-1,-1,-1},
    { 1, 0, 2,-1,-1,-1},
    { 4, 0, 3,-1,-1,-1},
    { 1, 4, 2, 1, 3, 4},
    { 3, 1, 5,-1,-1,-1},
    { 2, 3, 0, 2, 5, 3},
    { 1, 4, 0, 1, 5, 4},
    { 4, 2, 5,-1,-1,-1},
    { 4, 5, 2,-1,-1,-1},
    { 4, 1, 0, 4, 5, 1},
    { 3, 2, 0, 3, 5, 2},
    { 1, 3, 5,-1,-1,-1},
    { 4, 1, 2, 4, 3, 1},
    { 3, 0, 4,-1,-1,-1},
    { 2, 0, 1,-1,-1,-1},
    {-1,-1,-1,-1,-1,-1}};

__device__ __forceinline__ unsigned bits32(int b)
{
    unsigned w0 = g_occw[b >> 5];
    unsigned w1 = g_occw[(b >> 5) + 1];
    return __funnelshift_r(w0, w1, b & 31);
}

// shuffle-based exclusive block scan; ALL 32 lanes of warp 0 run the reduction
// shuffles (partial-warp shuffle with full mask hangs). Trailing sync: loop-safe.
template<int NT>
__device__ __forceinline__ unsigned blk_exscan_u32(unsigned v, int tid, unsigned* tot)
{
    constexpr int NW = NT/32;
    __shared__ unsigned ws[NW];
    int lane = tid & 31, w = tid >> 5;
    unsigned x = v;
#pragma unroll
    for (int o = 1; o < 32; o <<= 1) {
        unsigned y = __shfl_up_sync(0xffffffffu, x, o);
        if (lane >= o) x += y;
    }
    if (lane == 31) ws[w] = x;
    __syncthreads();
    if (w == 0) {
        unsigned t = (lane < NW) ? ws[lane] : 0u;
#pragma unroll
        for (int o = 1; o < NW; o <<= 1) {
            unsigned y = __shfl_up_sync(0xffffffffu, t, o);
            if (lane >= o) t += y;
        }
        if (lane < NW) ws[lane] = t;
    }
    __syncthreads();
    unsigned base = w ? ws[w-1] : 0u;
    *tot = ws[NW - 1];
    __syncthreads();
    return base + x - v;
}

template<int NT>
__device__ __forceinline__ unsigned long long blk_exscan_u64(unsigned long long v, int tid,
                                                             unsigned long long* tot)
{
    constexpr int NW = NT/32;
    __shared__ unsigned long long ws[NW];
    int lane = tid & 31, w = tid >> 5;
    unsigned long long x = v;
#pragma unroll
    for (int o = 1; o < 32; o <<= 1) {
        unsigned long long y = __shfl_up_sync(0xffffffffu, x, o);
        if (lane >= o) x += y;
    }
    if (lane == 31) ws[w] = x;
    __syncthreads();
    if (w == 0) {
        unsigned long long t = (lane < NW) ? ws[lane] : 0ull;
#pragma unroll
        for (int o = 1; o < NW; o <<= 1) {
            unsigned long long y = __shfl_up_sync(0xffffffffu, t, o);
            if (lane >= o) t += y;
        }
        if (lane < NW) ws[lane] = t;
    }
    __syncthreads();
    unsigned long long base = w ? ws[w-1] : 0ull;
    *tot = ws[NW - 1];
    __syncthreads();
    return base + x - v;
}

// last-block-done: returns true in exactly one block after all blocks arrive.
__device__ __forceinline__ bool last_block(unsigned* ctr, unsigned nb)
{
    __shared__ unsigned s_last;
    __threadfence();
    __syncthreads();
    if (threadIdx.x == 0) {
        unsigned prev = atomicAdd(ctr, 1u);
        if (prev == nb - 1u) { *ctr = 0u; s_last = 1u; }   // self-reset for replay
        else                 s_last = 0u;
    }
    __syncthreads();
    return s_last != 0u;
}

// ---------------- kernel 1: per-vertex prep + occ bit-pack + float4 packs ----------------
__global__ void k_prep(const float* __restrict__ feats,
                       const float* __restrict__ sdf_n,
                       const float* __restrict__ dir,
                       const float* __restrict__ rotm,
                       const float* __restrict__ scales,
                       int N, float dscale)
{
    int v = blockIdx.x*blockDim.x + threadIdx.x;
    bool inb = v < N;
    float s = inb ? sdf_n[v] : -1.0f;
    unsigned bal = __ballot_sync(0xffffffffu, s > 0.0f);
    if ((threadIdx.x & 31) == 0) g_occw[v >> 5] = bal;
    if (!inb) return;

    float ts = tanhf(s);
    float l0 = dscale * tanhf(dir[2*v+0]);
    float l1 = dscale * tanhf(dir[2*v+1]);
    const float* m = rotm + 9*(size_t)v;
    float sc = scales[v];
    g_va[v] = make_float4((m[0]*l0 + m[3]*l1 + m[6]) * sc,
                          (m[1]*l0 + m[4]*l1 + m[7]) * sc,
                          (m[2]*l0 + m[5]*l1 + m[8]) * sc, ts);
    const float* f = feats + (size_t)v * 6;
    g_vb[v] = make_float4(f[3], f[4], f[5], 0.0f);
}

// ---------------- kernel 2: edge-group masks + counts (+cube codes if NCeff>0) ----------------
__global__ void k_grp(int N, int S, int NG, int NCeff, int R)
{
    int t = blockIdx.x*blockDim.x + threadIdx.x;
    int S2 = S*S;

    if (t < NG) {
        int v0 = t << 5;
        int i0 = v0 / S2; int rem = v0 - i0*S2; int j0 = rem / S; int k0 = rem - j0*S;
        int qw = S - k0;
        unsigned pre = (qw >= 32) ? 0xffffffffu : ((1u << (qw & 31)) - 1u);
        int j1 = j0 + 1, i1 = i0; if (j1 == S) { j1 = 0; ++i1; }
        int nvld = N - v0;
        unsigned tailm = (nvld >= 32) ? 0xffffffffu : ((1u << (nvld & 31)) - 1u);
        unsigned A = bits32(v0);
        unsigned mm[7]; int cnt = 0;
#pragma unroll
        for (int tt = 1; tt <= 7; ++tt) {
            int di = (tt>>2)&1, dj = (tt>>1)&1, dk = tt&1;
            int d = di*S2 + dj*S + dk;
            unsigned X = A ^ bits32(v0 + d);
            unsigned vm = (((i0+di < S) && (j0+dj < S)) ? pre : 0u)
                        | (((i1+di < S) && (j1+dj < S)) ? ~pre : 0u);
            if (dk && (qw - 1) < 32) vm &= ~(1u << (qw - 1));
            vm &= tailm;
            mm[tt-1] = X & vm;
            cnt += __popc(mm[tt-1]);
        }
        g_egrp[2*t]   = make_uint4(mm[0], mm[1], mm[2], mm[3]);
        g_egrp[2*t+1] = make_uint4(mm[4], mm[5], mm[6], 0u);
        g_eGrpCnt[t]  = cnt;
    }

    if (t < NCeff) {          // generic fallback only (fast path computes codes in k_rankscan)
        int R2 = R*R;
        int i = t / R2; int rem = t - i*R2; int j = rem / R; int k = rem - j*R;
        int b = (i*S + j)*S + k;
        unsigned p00 = bits32(b)          & 3u;
        unsigned p01 = bits32(b + S)      & 3u;
        unsigned p10 = bits32(b + S2)     & 3u;
        unsigned p11 = bits32(b + S2 + S) & 3u;
        g_cubeCode[t] = (unsigned char)(p00 | (p01 << 2) | (p10 << 4) | (p11 << 6));
    }

    // last arriving block: exclusive scan over group counts (L2-hot)
    if (last_block(&g_done1, gridDim.x)) {
        int tid = threadIdx.x;
        int K = (NG + SCAN_B - 1) / SCAN_B;
        int base = tid * K;
        int run = 0;
        for (int it = 0; it < K; ++it) {
            int idx = base + it;
            if (idx < NG) run += g_eGrpCnt[idx];
        }
        unsigned tot;
        unsigned exc = blk_exscan_u32<SCAN_B>((unsigned)run, tid, &tot);
        int acc = (int)exc;
        for (int it = 0; it < K; ++it) {
            int idx = base + it;
            if (idx < NG) {
                int c = g_eGrpCnt[idx];
                ((unsigned*)g_egrp)[idx*8 + 7] = (unsigned)acc;
                acc += c;
            }
        }
        if (tid == 0) g_nv = (int)tot;
    }
}

// ---------------- kernel 3: rank table + edge list + tet scan (+cube codes fast) ----------------
__global__ void k_rankscan(int NG, int nRB, int T, int R, int nCh, int S,
                           int rbR, int fastT)
{
    int tid = threadIdx.x;
    int S2 = S*S;

    if (blockIdx.x < nRB) {
        // ---- one warp per 32-anchor group: compute ranks ----
        int g = blockIdx.x*8 + (tid >> 5);
        if (g < NG) {
            int lane = tid & 31;
            uint4 Aa = g_egrp[2*g], Bb = g_egrp[2*g+1];
            unsigned mm[7] = {Aa.x, Aa.y, Aa.z, Aa.w, Bb.x, Bb.y, Bb.z};
            unsigned low = (1u << lane) - 1u;
            int cum = (int)Bb.w;
#pragma unroll
            for (int x = 0; x < 7; ++x) cum += __popc(mm[x] & low);
            int v = (g << 5) + lane;
            int part = 0;
#pragma unroll
            for (int t = 0; t < 7; ++t) {
                if ((mm[t] >> lane) & 1u) {
                    int rank = cum + part; ++part;
                    g_edgeRank[t*NMAXV + v] = rank;
                    g_edgeList[rank] = (v << 3) | (t + 1);
                }
            }
        }
    } else if (fastT) {
        // ---- FAST tet path: uniform perm per chunk; codes from occ bits ----
        int ch = blockIdx.x - nRB;
        int base = ch*TCH + tid*SCAN_I;        // multiple of 8
        int p  = base >> (3*rbR);
        int c0 = base & ((1 << (3*rbR)) - 1);
        int i  = c0 >> (2*rbR);
        int rem = c0 & ((1 << (2*rbR)) - 1);
        int j = rem >> rbR, k = rem & (R - 1);
        int b = (i*S + j)*S + k;
        unsigned w00 = bits32(b), w01 = bits32(b + S);
        unsigned w10 = bits32(b + S2), w11 = bits32(b + S2 + S);
        int P0 = c_path[p][0], P1 = c_path[p][1], P2 = c_path[p][2], P3 = c_path[p][3];
        unsigned codes0 = 0u, codes1 = 0u;
        unsigned loc[SCAN_I], sum = 0u;
#pragma unroll
        for (int x = 0; x < SCAN_I; ++x) {
            unsigned code = ((w00 >> x) & 3u) | (((w01 >> x) & 3u) << 2)
                          | (((w10 >> x) & 3u) << 4) | (((w11 >> x) & 3u) << 6);
            if (x < 4) codes0 |= code << (8*x); else codes1 |= code << (8*(x-4));
            int ti = ((code >> P0) & 1) | (((code >> P1) & 1) << 1)
                   | (((code >> P2) & 1) << 2) | (((code >> P3) & 1) << 3);
            int nt = (int)((NT_PACK >> (ti << 1)) & 3u);
            unsigned add = (unsigned)(nt & 1) | ((unsigned)(nt >> 1) << 16);
            loc[x] = sum; sum += add;
        }
        if (p == 0) *(uint2*)(g_cubeCode + c0) = make_uint2(codes0, codes1);
        unsigned tot;
        unsigned exc = blk_exscan_u32<SCAN_B>(sum, tid, &tot);
#pragma unroll
        for (int x = 0; x < SCAN_I; ++x) g_tetScan[base + x] = exc + loc[x];
        if (tid == SCAN_B-1) g_tBlkP[ch] = tot;
    } else {
        // ---- generic tet path (cubeCode from k_grp) ----
        int ch = blockIdx.x - nRB;
        int base = ch*TCH + tid*SCAN_I;
        int R3 = R*R*R;
        unsigned loc[SCAN_I], sum = 0u;
#pragma unroll
        for (int it = 0; it < SCAN_I; ++it) {
            int r = base + it;
            unsigned add = 0u;
            if (r < T) {
                int p = r / R3, c = r - p*R3;
                unsigned code = g_cubeCode[c];
                int ti = ((code >> c_path[p][0]) & 1)
                       | (((code >> c_path[p][1]) & 1) << 1)
                       | (((code >> c_path[p][2]) & 1) << 2)
                       | (((code >> c_path[p][3]) & 1) << 3);
                int nt = (int)((NT_PACK >> (ti << 1)) & 3u);
                add = (unsigned)(nt & 1) | ((unsigned)(nt >> 1) << 16);
            }
            loc[it] = sum; sum += add;
        }
        unsigned tot;
        unsigned exc = blk_exscan_u32<SCAN_B>(sum, tid, &tot);
#pragma unroll
        for (int it = 0; it < SCAN_I; ++it) {
            int r = base + it;
            if (r < T) g_tetScan[r] = exc + loc[it];
        }
        if (tid == SCAN_B-1) g_tBlkP[ch] = tot;
    }

    // last arriving block: exclusive scan of chunk sums
    if (last_block(&g_done2, gridDim.x)) {
        int K = (nCh + SCAN_B - 1) / SCAN_B;
        int b0 = tid * K;
        unsigned long long run = 0ull;
        for (int it = 0; it < K; ++it) {
            int idx = b0 + it;
            if (idx < nCh) {
                unsigned pkt = g_tBlkP[idx];
                run += (unsigned long long)(pkt & 0xffffu)
                     + ((unsigned long long)(pkt >> 16) << 32);
            }
        }
        unsigned long long tot64;
        unsigned long long exc64 = blk_exscan_u64<SCAN_B>(run, tid, &tot64);
        unsigned long long acc = exc64;
        for (int it = 0; it < K; ++it) {
            int idx = b0 + it;
            if (idx < nCh) {
                unsigned pkt = g_tBlkP[idx];
                g_tBlk64[idx] = acc;
                acc += (unsigned long long)(pkt & 0xffffu)
                     + ((unsigned long long)(pkt >> 16) << 32);
            }
        }
        if (tid == 0) g_n1 = (int)(tot64 & 0xffffffffull);
    }
}

// ---------------- kernel 4: fused emit — verts (rank-dense) + faces ----------------
__global__ void k_emit(float* __restrict__ out,
                       int nVB, int T, int R, int S, int rbR /* log2 R or -1 */)
{
    int tid = threadIdx.x;
    int S2 = S*S;

    if (blockIdx.x < nVB) {
        // ===== vertex emit: thread-per-output-vertex, smem-staged dense stores =====
        __shared__ float sm[SCAN_B * 6];
        int nv = g_nv;
        int b0 = blockIdx.x * SCAN_B;
        if (b0 >= nv) return;
        int cnt = nv - b0; if (cnt > SCAN_B) cnt = SCAN_B;
        int idx = b0 + tid;
        if (tid < cnt) {
            int packed = g_edgeList[idx];
            int v = packed >> 3, t = packed & 7;
            int v2 = v + ((t>>2)&1)*S2 + ((t>>1)&1)*S + (t&1);
            float4 A  = g_va[v];
            float4 A2 = g_va[v2];
            float4 B  = g_vb[v];
            float4 B2 = g_vb[v2];
            float inv = 1.0f / (A.w - A2.w);
            float wa = -A2.w * inv, wb = A.w * inv;
            float* o = sm + tid*6;
            o[0] = wa*A.x + wb*A2.x;
            o[1] = wa*A.y + wb*A2.y;
            o[2] = wa*A.z + wb*A2.z;
            o[3] = wa*B.x + wb*B2.x;
            o[4] = wa*B.y + wb*B2.y;
            o[5] = wa*B.z + wb*B2.z;
        }
        __syncthreads();
        float2* dst = (float2*)(out + (size_t)b0 * 6);
        const float2* src = (const float2*)sm;
        int nf2 = 3 * cnt;
        for (int i = tid; i < nf2; i += SCAN_B) dst[i] = src[i];
        return;
    }

    // ===== faces: warp-uniform edge types -> coalesced rank loads =====
    int r = (blockIdx.x - nVB)*SCAN_B + tid;
    if (r >= T) return;
    int p, c, i, j, k;
    if (rbR >= 0) {
        p = r >> (3*rbR);  c = r & ((1 << (3*rbR)) - 1);
        i = c >> (2*rbR);  int rem = c & ((1 << (2*rbR)) - 1);
        j = rem >> rbR;    k = rem & (R - 1);
    } else {
        int R3 = R*R*R, R2 = R*R;
        p = r / R3; c = r - p*R3;
        i = c / R2; int rem = c - i*R2; j = rem / R; k = rem - j*R;
    }
    unsigned code = g_cubeCode[c];
    int P0 = c_path[p][0], P1 = c_path[p][1], P2 = c_path[p][2], P3 = c_path[p][3];
    int ti = ((code >> P0) & 1) | (((code >> P1) & 1) << 1)
           | (((code >> P2) & 1) << 2) | (((code >> P3) & 1) << 3);
    int nt = (int)((NT_PACK >> (ti << 1)) & 3u);
    if (!nt) return;

    int v000 = (i*S + j)*S + k;
    int PP[4] = {P0, P1, P2, P3};
    const int ea[6] = {0,0,0,1,1,2};
    const int eb[6] = {1,2,3,2,3,3};

    // Load ALL 6 edge ranks: slot s has warp-uniform type and consecutive va.
    int er[6];
#pragma unroll
    for (int s = 0; s < 6; ++s) {
        int na = PP[ea[s]], nbn = PP[eb[s]];
        int va = v000 + ((na>>2)&1)*S2 + ((na>>1)&1)*S + (na&1);
        er[s] = g_edgeRank[((na ^ nbn) - 1)*NMAXV + va];
    }

    unsigned sc = g_tetScan[r];
    unsigned long long bk = g_tBlk64[r / TCH];
    size_t vbase = (size_t)g_nv * 6;
    const int* tt = c_tri[ti];

    int s1 = (int)(sc & 0xffffu) + (int)(unsigned)(bk & 0xffffffffull);
    int s2 = (int)(sc >> 16)     + (int)(unsigned)(bk >> 32);
    size_t o = (nt == 1) ? vbase + (size_t)s1 * 3
                         : vbase + ((size_t)g_n1 + 2*(size_t)s2) * 3;
    out[o+0] = (float)er[tt[0]];
    out[o+1] = (float)er[tt[1]];
    out[o+2] = (float)er[tt[2]];
    if (nt == 2) {
        out[o+3] = (float)er[tt[3]];
        out[o+4] = (float)er[tt[4]];
        out[o+5] = (float)er[tt[5]];
    }
}

// ---------------- launch ----------------
extern "C" void kernel_launch(void* const* d_in, const int* in_sizes, int n_in,
                              void* d_out, int out_size)
{
    const float* feats  = (const float*)d_in[0];
    const float* sdf_n  = (const float*)d_in[1];
    const float* dir    = (const float*)d_in[2];
    const float* rotm   = (const float*)d_in[3];
    const float* scales = (const float*)d_in[4];

    int N = in_sizes[1];
    int S = 1;
    while ((long long)S*S*S < (long long)N) ++S;   // S = R+1
    int R = S - 1;
    int E = 7*N;
    int T = 6*R*R*R;
    int NC = R*R*R;
    int NG = (N + 31) >> 5;
    int nCh = (T + TCH - 1) / TCH;
    float dscale = 4.0f / (float)R;
    float* out = (float*)d_out;

    int rbR = -1;
    if ((R & (R-1)) == 0) { rbR = 0; while ((1 << rbR) < R) ++rbR; }
    int R3 = R*R*R;
    int fastT = (rbR >= 0 && (R3 % TCH) == 0 && (R % 8) == 0) ? 1 : 0;

    int NCeff = fastT ? 0 : NC;                    // cube codes in k_grp only if generic
    int ngrp  = fastT ? NG : ((NC > NG) ? NC : NG);
    int nRB   = (NG + 7) / 8;                      // rank blocks (8 warps/block)
    int nVB   = (E + SCAN_B - 1) / SCAN_B;         // vertex-emit blocks (covers worst case)
    int nFB   = (T + SCAN_B - 1) / SCAN_B;         // face blocks

    k_prep    <<<(N + 255)/256, 256>>>(feats, sdf_n, dir, rotm, scales, N, dscale);
    k_grp     <<<(ngrp + 255)/256, 256>>>(N, S, NG, NCeff, R);
    k_rankscan<<<nRB + nCh, SCAN_B>>>(NG, nRB, T, R, nCh, S, rbR, fastT);
    k_emit    <<<nVB + nFB, SCAN_B>>>(out, nVB, T, R, S, rbR);
}

// round 14
// speedup vs baseline: 1.4718x; 1.0353x over previous
#include <cuda_runtime.h>
#include <math.h>

// ---------------- static scratch ----------------
#define SMAX   65
#define NMAXV  (SMAX*SMAX*SMAX)       // 274625 vertices
#define NWPAD  8832                   // occ bit-words + pad
#define NGMAX  9216                   // 32-anchor edge groups (padded)
#define NCMAX  (64*64*64)             // cubes
#define TMAXT  (6*NCMAX)              // tets
#define SCAN_B 256
#define SCAN_I 8
#define TCH    (SCAN_B*SCAN_I)        // 2048 tets per chunk
#define MAXCH  1024
#define NT_PACK 0x16696994u           // 2-bit ntri LUT (verified vs triangle table)

__device__ unsigned           g_occw[NWPAD];
__device__ float4             g_va[NMAXV];        // (rot0, rot1, rot2, tanh_sdf)
__device__ float4             g_vb[NMAXV];        // (col0, col1, col2, 0)
__device__ uint4              g_egrp[NGMAX*2];    // 7 masks + exclusive base
__device__ int                g_eGrpCnt[NGMAX];
__device__ unsigned char      g_cubeCode[NCMAX];
__device__ int                g_edgeRank[7*NMAXV]; // TYPE-MAJOR: [t][v]
__device__ int                g_edgeList[7*NMAXV]; // packed (v<<3)|type per rank
__device__ unsigned           g_tetScan[TMAXT];   // packed (cnt1 lo16 | cnt2 hi16)
__device__ unsigned           g_tBlkP[MAXCH];
__device__ unsigned long long g_tBlk64[MAXCH];
__device__ unsigned           d_triE[96];         // packed per-(perm,ti) er19 indices
__device__ int                g_nv;
__device__ int                g_n1;
__device__ unsigned           g_done1;            // last-block counters (self-reset)
__device__ unsigned           g_done2;

__constant__ int c_path[6][4] = {
    {0,4,6,7},{0,4,5,7},{0,2,6,7},{0,2,3,7},{0,1,5,7},{0,1,3,7}};
__constant__ int c_tri[16][6] = {
    {-1,-1,-1,-1,-1,-1},
    { 1, 0, 2,-1,-1,-1},
    { 4, 0, 3,-1,-1,-1},
    { 1, 4, 2, 1, 3, 4},
    { 3, 1, 5,-1,-1,-1},
    { 2, 3, 0, 2, 5, 3},
    { 1, 4, 0, 1, 5, 4},
    { 4, 2, 5,-1,-1,-1},
    { 4, 5, 2,-1,-1,-1},
    { 4, 1, 0, 4, 5, 1},
    { 3, 2, 0, 3, 5, 2},
    { 1, 3, 5,-1,-1,-1},
    { 4, 1, 2, 4, 3, 1},
    { 3, 0, 4,-1,-1,-1},
    { 2, 0, 1,-1,-1,-1},
    {-1,-1,-1,-1,-1,-1}};
// slot (pairs (0,1)(0,2)(0,3)(1,2)(1,3)(2,3) of path corners) -> index in 19-edge list
__constant__ int c_s2e[6][6] = {
    {3,5,6,15,16,18},
    {3,4,6,14,16,17},
    {1,5,6,11,12,18},
    {1,2,6,10,12,13},
    {0,4,6, 8, 9,17},
    {0,2,6, 7, 9,13}};

__device__ __forceinline__ unsigned bits32(int b)
{
    unsigned w0 = g_occw[b >> 5];
    unsigned w1 = g_occw[(b >> 5) + 1];
    return __funnelshift_r(w0, w1, b & 31);
}

// shuffle-based exclusive block scan; ALL 32 lanes of warp 0 run the reduction
// shuffles (partial-warp shuffle with full mask hangs). Trailing sync: loop-safe.
template<int NT>
__device__ __forceinline__ unsigned blk_exscan_u32(unsigned v, int tid, unsigned* tot)
{
    constexpr int NW = NT/32;
    __shared__ unsigned ws[NW];
    int lane = tid & 31, w = tid >> 5;
    unsigned x = v;
#pragma unroll
    for (int o = 1; o < 32; o <<= 1) {
        unsigned y = __shfl_up_sync(0xffffffffu, x, o);
        if (lane >= o) x += y;
    }
    if (lane == 31) ws[w] = x;
    __syncthreads();
    if (w == 0) {
        unsigned t = (lane < NW) ? ws[lane] : 0u;
#pragma unroll
        for (int o = 1; o < NW; o <<= 1) {
            unsigned y = __shfl_up_sync(0xffffffffu, t, o);
            if (lane >= o) t += y;
        }
        if (lane < NW) ws[lane] = t;
    }
    __syncthreads();
    unsigned base = w ? ws[w-1] : 0u;
    *tot = ws[NW - 1];
    __syncthreads();
    return base + x - v;
}

template<int NT>
__device__ __forceinline__ unsigned long long blk_exscan_u64(unsigned long long v, int tid,
                                                             unsigned long long* tot)
{
    constexpr int NW = NT/32;
    __shared__ unsigned long long ws[NW];
    int lane = tid & 31, w = tid >> 5;
    unsigned long long x = v;
#pragma unroll
    for (int o = 1; o < 32; o <<= 1) {
        unsigned long long y = __shfl_up_sync(0xffffffffu, x, o);
        if (lane >= o) x += y;
    }
    if (lane == 31) ws[w] = x;
    __syncthreads();
    if (w == 0) {
        unsigned long long t = (lane < NW) ? ws[lane] : 0ull;
#pragma unroll
        for (int o = 1; o < NW; o <<= 1) {
            unsigned long long y = __shfl_up_sync(0xffffffffu, t, o);
            if (lane >= o) t += y;
        }
        if (lane < NW) ws[lane] = t;
    }
    __syncthreads();
    unsigned long long base = w ? ws[w-1] : 0ull;
    *tot = ws[NW - 1];
    __syncthreads();
    return base + x - v;
}

// last-block-done: returns true in exactly one block after all blocks arrive.
__device__ __forceinline__ bool last_block(unsigned* ctr, unsigned nb)
{
    __shared__ unsigned s_last;
    __threadfence();
    __syncthreads();
    if (threadIdx.x == 0) {
        unsigned prev = atomicAdd(ctr, 1u);
        if (prev == nb - 1u) { *ctr = 0u; s_last = 1u; }   // self-reset for replay
        else                 s_last = 0u;
    }
    __syncthreads();
    return s_last != 0u;
}

// ---------------- kernel 1: per-vertex prep + occ bit-pack + float4 packs ----------------
__global__ void k_prep(const float* __restrict__ feats,
                       const float* __restrict__ sdf_n,
                       const float* __restrict__ dir,
                       const float* __restrict__ rotm,
                       const float* __restrict__ scales,
                       int N, float dscale)
{
    int v = blockIdx.x*blockDim.x + threadIdx.x;
    bool inb = v < N;
    float s = inb ? sdf_n[v] : -1.0f;
    unsigned bal = __ballot_sync(0xffffffffu, s > 0.0f);
    if ((threadIdx.x & 31) == 0) g_occw[v >> 5] = bal;
    if (!inb) return;

    float ts = tanhf(s);
    float l0 = dscale * tanhf(dir[2*v+0]);
    float l1 = dscale * tanhf(dir[2*v+1]);
    const float* m = rotm + 9*(size_t)v;
    float sc = scales[v];
    g_va[v] = make_float4((m[0]*l0 + m[3]*l1 + m[6]) * sc,
                          (m[1]*l0 + m[4]*l1 + m[7]) * sc,
                          (m[2]*l0 + m[5]*l1 + m[8]) * sc, ts);
    const float* f = feats + (size_t)v * 6;
    g_vb[v] = make_float4(f[3], f[4], f[5], 0.0f);
}

// ---------------- kernel 2: edge-group masks + counts (+cube codes if NCeff>0) ----------------
__global__ void k_grp(int N, int S, int NG, int NCeff, int R)
{
    int t = blockIdx.x*blockDim.x + threadIdx.x;
    int S2 = S*S;

    if (t < NG) {
        int v0 = t << 5;
        int i0 = v0 / S2; int rem = v0 - i0*S2; int j0 = rem / S; int k0 = rem - j0*S;
        int qw = S - k0;
        unsigned pre = (qw >= 32) ? 0xffffffffu : ((1u << (qw & 31)) - 1u);
        int j1 = j0 + 1, i1 = i0; if (j1 == S) { j1 = 0; ++i1; }
        int nvld = N - v0;
        unsigned tailm = (nvld >= 32) ? 0xffffffffu : ((1u << (nvld & 31)) - 1u);
        unsigned A = bits32(v0);
        unsigned mm[7]; int cnt = 0;
#pragma unroll
        for (int tt = 1; tt <= 7; ++tt) {
            int di = (tt>>2)&1, dj = (tt>>1)&1, dk = tt&1;
            int d = di*S2 + dj*S + dk;
            unsigned X = A ^ bits32(v0 + d);
            unsigned vm = (((i0+di < S) && (j0+dj < S)) ? pre : 0u)
                        | (((i1+di < S) && (j1+dj < S)) ? ~pre : 0u);
            if (dk && (qw - 1) < 32) vm &= ~(1u << (qw - 1));
            vm &= tailm;
            mm[tt-1] = X & vm;
            cnt += __popc(mm[tt-1]);
        }
        g_egrp[2*t]   = make_uint4(mm[0], mm[1], mm[2], mm[3]);
        g_egrp[2*t+1] = make_uint4(mm[4], mm[5], mm[6], 0u);
        g_eGrpCnt[t]  = cnt;
    }

    if (t < NCeff) {          // generic fallback only (fast path computes codes in k_rankscan)
        int R2 = R*R;
        int i = t / R2; int rem = t - i*R2; int j = rem / R; int k = rem - j*R;
        int b = (i*S + j)*S + k;
        unsigned p00 = bits32(b)          & 3u;
        unsigned p01 = bits32(b + S)      & 3u;
        unsigned p10 = bits32(b + S2)     & 3u;
        unsigned p11 = bits32(b + S2 + S) & 3u;
        g_cubeCode[t] = (unsigned char)(p00 | (p01 << 2) | (p10 << 4) | (p11 << 6));
    }

    // last arriving block: exclusive scan over group counts + build d_triE
    if (last_block(&g_done1, gridDim.x)) {
        int tid = threadIdx.x;
        if (tid < 96) {
            int p = tid >> 4, ti = tid & 15;
            unsigned pk = 0u;
            for (int q = 0; q < 6; ++q) {
                int sl = c_tri[ti][q];
                int e  = (sl >= 0) ? c_s2e[p][sl] : 0;
                pk |= (unsigned)e << (5*q);
            }
            d_triE[tid] = pk;
        }
        int K = (NG + SCAN_B - 1) / SCAN_B;
        int base = tid * K;
        int run = 0;
        for (int it = 0; it < K; ++it) {
            int idx = base + it;
            if (idx < NG) run += g_eGrpCnt[idx];
        }
        unsigned tot;
        unsigned exc = blk_exscan_u32<SCAN_B>((unsigned)run, tid, &tot);
        int acc = (int)exc;
        for (int it = 0; it < K; ++it) {
            int idx = base + it;
            if (idx < NG) {
                int c = g_eGrpCnt[idx];
                ((unsigned*)g_egrp)[idx*8 + 7] = (unsigned)acc;
                acc += c;
            }
        }
        if (tid == 0) g_nv = (int)tot;
    }
}

// ---------------- kernel 3: rank table + edge list + tet scan (+cube codes fast) ----------------
__global__ void k_rankscan(int NG, int nRB, int T, int R, int nCh, int S,
                           int rbR, int fastT)
{
    int tid = threadIdx.x;
    int S2 = S*S;

    if (blockIdx.x < nRB) {
        // ---- one warp per 32-anchor group: compute ranks ----
        int g = blockIdx.x*8 + (tid >> 5);
        if (g < NG) {
            int lane = tid & 31;
            uint4 Aa = g_egrp[2*g], Bb = g_egrp[2*g+1];
            unsigned mm[7] = {Aa.x, Aa.y, Aa.z, Aa.w, Bb.x, Bb.y, Bb.z};
            unsigned low = (1u << lane) - 1u;
            int cum = (int)Bb.w;
#pragma unroll
            for (int x = 0; x < 7; ++x) cum += __popc(mm[x] & low);
            int v = (g << 5) + lane;
            int part = 0;
#pragma unroll
            for (int t = 0; t < 7; ++t) {
                if ((mm[t] >> lane) & 1u) {
                    int rank = cum + part; ++part;
                    g_edgeRank[t*NMAXV + v] = rank;
                    g_edgeList[rank] = (v << 3) | (t + 1);
                }
            }
        }
    } else if (fastT) {
        // ---- FAST tet path: uniform perm per chunk; codes from occ bits ----
        int ch = blockIdx.x - nRB;
        int base = ch*TCH + tid*SCAN_I;        // multiple of 8
        int p  = base >> (3*rbR);
        int c0 = base & ((1 << (3*rbR)) - 1);
        int i  = c0 >> (2*rbR);
        int rem = c0 & ((1 << (2*rbR)) - 1);
        int j = rem >> rbR, k = rem & (R - 1);
        int b = (i*S + j)*S + k;
        unsigned w00 = bits32(b), w01 = bits32(b + S);
        unsigned w10 = bits32(b + S2), w11 = bits32(b + S2 + S);
        int P0 = c_path[p][0], P1 = c_path[p][1], P2 = c_path[p][2], P3 = c_path[p][3];
        unsigned codes0 = 0u, codes1 = 0u;
        unsigned loc[SCAN_I], sum = 0u;
#pragma unroll
        for (int x = 0; x < SCAN_I; ++x) {
            unsigned code = ((w00 >> x) & 3u) | (((w01 >> x) & 3u) << 2)
                          | (((w10 >> x) & 3u) << 4) | (((w11 >> x) & 3u) << 6);
            if (x < 4) codes0 |= code << (8*x); else codes1 |= code << (8*(x-4));
            int ti = ((code >> P0) & 1) | (((code >> P1) & 1) << 1)
                   | (((code >> P2) & 1) << 2) | (((code >> P3) & 1) << 3);
            int nt = (int)((NT_PACK >> (ti << 1)) & 3u);
            unsigned add = (unsigned)(nt & 1) | ((unsigned)(nt >> 1) << 16);
            loc[x] = sum; sum += add;
        }
        if (p == 0) *(uint2*)(g_cubeCode + c0) = make_uint2(codes0, codes1);
        unsigned tot;
        unsigned exc = blk_exscan_u32<SCAN_B>(sum, tid, &tot);
#pragma unroll
        for (int x = 0; x < SCAN_I; ++x) g_tetScan[base + x] = exc + loc[x];
        if (tid == SCAN_B-1) g_tBlkP[ch] = tot;
    } else {
        // ---- generic tet path (cubeCode from k_grp) ----
        int ch = blockIdx.x - nRB;
        int base = ch*TCH + tid*SCAN_I;
        int R3 = R*R*R;
        unsigned loc[SCAN_I], sum = 0u;
#pragma unroll
        for (int it = 0; it < SCAN_I; ++it) {
            int r = base + it;
            unsigned add = 0u;
            if (r < T) {
                int p = r / R3, c = r - p*R3;
                unsigned code = g_cubeCode[c];
                int ti = ((code >> c_path[p][0]) & 1)
                       | (((code >> c_path[p][1]) & 1) << 1)
                       | (((code >> c_path[p][2]) & 1) << 2)
                       | (((code >> c_path[p][3]) & 1) << 3);
                int nt = (int)((NT_PACK >> (ti << 1)) & 3u);
                add = (unsigned)(nt & 1) | ((unsigned)(nt >> 1) << 16);
            }
            loc[it] = sum; sum += add;
        }
        unsigned tot;
        unsigned exc = blk_exscan_u32<SCAN_B>(sum, tid, &tot);
#pragma unroll
        for (int it = 0; it < SCAN_I; ++it) {
            int r = base + it;
            if (r < T) g_tetScan[r] = exc + loc[it];
        }
        if (tid == SCAN_B-1) g_tBlkP[ch] = tot;
    }

    // last arriving block: exclusive scan of chunk sums
    if (last_block(&g_done2, gridDim.x)) {
        int K = (nCh + SCAN_B - 1) / SCAN_B;
        int b0 = tid * K;
        unsigned long long run = 0ull;
        for (int it = 0; it < K; ++it) {
            int idx = b0 + it;
            if (idx < nCh) {
                unsigned pkt = g_tBlkP[idx];
                run += (unsigned long long)(pkt & 0xffffu)
                     + ((unsigned long long)(pkt >> 16) << 32);
            }
        }
        unsigned long long tot64;
        unsigned long long exc64 = blk_exscan_u64<SCAN_B>(run, tid, &tot64);
        unsigned long long acc = exc64;
        for (int it = 0; it < K; ++it) {
            int idx = b0 + it;
            if (idx < nCh) {
                unsigned pkt = g_tBlkP[idx];
                g_tBlk64[idx] = acc;
                acc += (unsigned long long)(pkt & 0xffffu)
                     + ((unsigned long long)(pkt >> 16) << 32);
            }
        }
        if (tid == 0) g_n1 = (int)(tot64 & 0xffffffffull);
    }
}

// ---------------- kernel 4: vertex emit (rank-dense, smem-staged) ----------------
__global__ void k_vemit(float* __restrict__ out, int S)
{
    __shared__ float sm[SCAN_B * 6];
    int tid = threadIdx.x;
    int S2 = S*S;
    int nv = g_nv;
    int b0 = blockIdx.x * SCAN_B;
    if (b0 >= nv) return;
    int cnt = nv - b0; if (cnt > SCAN_B) cnt = SCAN_B;
    int idx = b0 + tid;
    if (tid < cnt) {
        int packed = g_edgeList[idx];
        int v = packed >> 3, t = packed & 7;
        int v2 = v + ((t>>2)&1)*S2 + ((t>>1)&1)*S + (t&1);
        float4 A  = g_va[v];
        float4 A2 = g_va[v2];
        float4 B  = g_vb[v];
        float4 B2 = g_vb[v2];
        float inv = 1.0f / (A.w - A2.w);
        float wa = -A2.w * inv, wb = A.w * inv;
        float* o = sm + tid*6;
        o[0] = wa*A.x + wb*A2.x;
        o[1] = wa*A.y + wb*A2.y;
        o[2] = wa*A.z + wb*A2.z;
        o[3] = wa*B.x + wb*B2.x;
        o[4] = wa*B.y + wb*B2.y;
        o[5] = wa*B.z + wb*B2.z;
    }
    __syncthreads();
    float2* dst = (float2*)(out + (size_t)b0 * 6);
    const float2* src = (const float2*)sm;
    int nf2 = 3 * cnt;
    for (int i = tid; i < nf2; i += SCAN_B) dst[i] = src[i];
}

// ---------------- kernel 5: face emit, one thread per CUBE (19 shared edges) ----------------
__global__ void k_femit(float* __restrict__ out,
                        int NC, int R, int S, int rbR, int R3)
{
    __shared__ int ser[SCAN_B * 19];     // per-thread 19 ranks; stride 19 -> conflict-free
    int tid = threadIdx.x;
    int c = blockIdx.x*SCAN_B + tid;
    if (c >= NC) return;                 // no cross-thread smem use: early return safe

    unsigned code = g_cubeCode[c];
    int tis[6], nts[6]; int total = 0;
#pragma unroll
    for (int p = 0; p < 6; ++p) {
        int ti = ((code >> c_path[p][0]) & 1) | (((code >> c_path[p][1]) & 1) << 1)
               | (((code >> c_path[p][2]) & 1) << 2) | (((code >> c_path[p][3]) & 1) << 3);
        tis[p] = ti;
        int nt = (int)((NT_PACK >> (ti << 1)) & 3u);
        nts[p] = nt; total += nt;
    }
    if (!total) return;

    int i, j, k;
    if (rbR >= 0) {
        i = c >> (2*rbR); int rem = c & ((1 << (2*rbR)) - 1);
        j = rem >> rbR;   k = rem & (R - 1);
    } else {
        int R2 = R*R;
        i = c / R2; int rem = c - i*R2; j = rem / R; k = rem - j*R;
    }
    int S2 = S*S;
    int v000 = (i*S + j)*S + k;
    // corner offsets for anchors 0..6
    int uo[7] = {0, 1, S, S+1, S2, S2+1, S2+S};
    // 19-edge list: anchor corner + (type-1), compile-time indices
    const int eu[19] = {0,0,0,0,0,0,0, 1,1,1, 2,2,2, 3, 4,4,4, 5, 6};
    const int et[19] = {0,1,2,3,4,5,6, 1,3,5, 0,3,4, 3, 0,1,2, 1, 0};
    int* my = ser + tid*19;
#pragma unroll
    for (int x = 0; x < 19; ++x)
        my[x] = g_edgeRank[et[x]*NMAXV + v000 + uo[eu[x]]];

    size_t vbase = (size_t)g_nv * 6;
    int n1 = g_n1;
#pragma unroll
    for (int p = 0; p < 6; ++p) {
        int nt = nts[p];
        if (!nt) continue;
        int r = p*R3 + c;
        unsigned sc = g_tetScan[r];
        unsigned long long bk = g_tBlk64[r / TCH];
        int s1 = (int)(sc & 0xffffu) + (int)(unsigned)(bk & 0xffffffffull);
        int s2 = (int)(sc >> 16)     + (int)(unsigned)(bk >> 32);
        unsigned epk = d_triE[(p << 4) + tis[p]];
        size_t o = (nt == 1) ? vbase + (size_t)s1 * 3
                             : vbase + ((size_t)n1 + 2*(size_t)s2) * 3;
        out[o+0] = (float)my[ epk        & 31u];
        out[o+1] = (float)my[(epk >> 5)  & 31u];
        out[o+2] = (float)my[(epk >> 10) & 31u];
        if (nt == 2) {
            out[o+3] = (float)my[(epk >> 15) & 31u];
            out[o+4] = (float)my[(epk >> 20) & 31u];
            out[o+5] = (float)my[(epk >> 25) & 31u];
        }
    }
}

// ---------------- launch ----------------
extern "C" void kernel_launch(void* const* d_in, const int* in_sizes, int n_in,
                              void* d_out, int out_size)
{
    const float* feats  = (const float*)d_in[0];
    const float* sdf_n  = (const float*)d_in[1];
    const float* dir    = (const float*)d_in[2];
    const float* rotm   = (const float*)d_in[3];
    const float* scales = (const float*)d_in[4];

    int N = in_sizes[1];
    int S = 1;
    while ((long long)S*S*S < (long long)N) ++S;   // S = R+1
    int R = S - 1;
    int E = 7*N;
    int T = 6*R*R*R;
    int NC = R*R*R;
    int NG = (N + 31) >> 5;
    int nCh = (T + TCH - 1) / TCH;
    float dscale = 4.0f / (float)R;
    float* out = (float*)d_out;

    int rbR = -1;
    if ((R & (R-1)) == 0) { rbR = 0; while ((1 << rbR) < R) ++rbR; }
    int R3 = R*R*R;
    int fastT = (rbR >= 0 && (R3 % TCH) == 0 && (R % 8) == 0) ? 1 : 0;

    int NCeff = fastT ? 0 : NC;                    // cube codes in k_grp only if generic
    int ngrp  = fastT ? NG : ((NC > NG) ? NC : NG);
    int nRB   = (NG + 7) / 8;                      // rank blocks (8 warps/block)
    int nVB   = (E + SCAN_B - 1) / SCAN_B;         // vertex-emit blocks (covers worst case)
    int nCB   = (NC + SCAN_B - 1) / SCAN_B;        // cube blocks for faces

    k_prep    <<<(N + 255)/256, 256>>>(feats, sdf_n, dir, rotm, scales, N, dscale);
    k_grp     <<<(ngrp + 255)/256, 256>>>(N, S, NG, NCeff, R);
    k_rankscan<<<nRB + nCh, SCAN_B>>>(NG, nRB, T, R, nCh, S, rbR, fastT);
    k_vemit   <<<nVB, SCAN_B>>>(out, S);
    k_femit   <<<nCB, SCAN_B>>>(out, NC, R, S, rbR, R3);
}

// round 15
// speedup vs baseline: 1.5193x; 1.0323x over previous
#include <cuda_runtime.h>
#include <math.h>

// ---------------- static scratch ----------------
#define SMAX   65
#define NMAXV  (SMAX*SMAX*SMAX)       // 274625 vertices
#define NWPAD  8832                   // occ bit-words + pad
#define NGMAX  9216                   // 32-anchor edge groups (padded)
#define NCMAX  (64*64*64)             // cubes
#define TMAXT  (6*NCMAX)              // tets
#define SCAN_B 256
#define SCAN_I 8
#define TCH    (SCAN_B*SCAN_I)        // 2048 tets per chunk
#define MAXCH  1024
#define NT_PACK 0x16696994u           // 2-bit ntri LUT (verified vs triangle table)

__device__ unsigned           g_occw[NWPAD];
__device__ float4             g_vab[2*NMAXV];     // [2v]=(rot0..2,tanh_sdf) [2v+1]=(col0..2,0)
__device__ uint4              g_egrp[NGMAX*2];    // 7 masks + exclusive base
__device__ int                g_eGrpCnt[NGMAX];
__device__ unsigned char      g_cubeCode[NCMAX];
__device__ int                g_edgeRank[7*NMAXV]; // TYPE-MAJOR: [t][v]
__device__ int                g_edgeList[7*NMAXV]; // packed (v<<3)|type per rank
__device__ unsigned           g_tetScan[TMAXT];   // packed (cnt1 lo16 | cnt2 hi16)
__device__ unsigned           g_tBlkP[MAXCH];
__device__ unsigned long long g_tBlk64[MAXCH];
__device__ unsigned           d_triE[96];         // packed per-(perm,ti) er19 indices
__device__ int                g_nv;
__device__ int                g_n1;
__device__ unsigned           g_done1;            // last-block counters (self-reset)
__device__ unsigned           g_done2;

__constant__ int c_path[6][4] = {
    {0,4,6,7},{0,4,5,7},{0,2,6,7},{0,2,3,7},{0,1,5,7},{0,1,3,7}};
__constant__ int c_tri[16][6] = {
    {-1,-1,-1,-1,-1,-1},
    { 1, 0, 2,-1,-1,-1},
    { 4, 0, 3,-1,-1,-1},
    { 1, 4, 2, 1, 3, 4},
    { 3, 1, 5,-1,-1,-1},
    { 2, 3, 0, 2, 5, 3},
    { 1, 4, 0, 1, 5, 4},
    { 4, 2, 5,-1,-1,-1},
    { 4, 5, 2,-1,-1,-1},
    { 4, 1, 0, 4, 5, 1},
    { 3, 2, 0, 3, 5, 2},
    { 1, 3, 5,-1,-1,-1},
    { 4, 1, 2, 4, 3, 1},
    { 3, 0, 4,-1,-1,-1},
    { 2, 0, 1,-1,-1,-1},
    {-1,-1,-1,-1,-1,-1}};
// slot (pairs (0,1)(0,2)(0,3)(1,2)(1,3)(2,3) of path corners) -> index in 19-edge list
__constant__ int c_s2e[6][6] = {
    {3,5,6,15,16,18},
    {3,4,6,14,16,17},
    {1,5,6,11,12,18},
    {1,2,6,10,12,13},
    {0,4,6, 8, 9,17},
    {0,2,6, 7, 9,13}};

__device__ __forceinline__ unsigned bits32(int b)
{
    unsigned w0 = g_occw[b >> 5];
    unsigned w1 = g_occw[(b >> 5) + 1];
    return __funnelshift_r(w0, w1, b & 31);
}

// shuffle-based exclusive block scan; ALL 32 lanes of warp 0 run the reduction
// shuffles (partial-warp shuffle with full mask hangs). Trailing sync: loop-safe.
template<int NT>
__device__ __forceinline__ unsigned blk_exscan_u32(unsigned v, int tid, unsigned* tot)
{
    constexpr int NW = NT/32;
    __shared__ unsigned ws[NW];
    int lane = tid & 31, w = tid >> 5;
    unsigned x = v;
#pragma unroll
    for (int o = 1; o < 32; o <<= 1) {
        unsigned y = __shfl_up_sync(0xffffffffu, x, o);
        if (lane >= o) x += y;
    }
    if (lane == 31) ws[w] = x;
    __syncthreads();
    if (w == 0) {
        unsigned t = (lane < NW) ? ws[lane] : 0u;
#pragma unroll
        for (int o = 1; o < NW; o <<= 1) {
            unsigned y = __shfl_up_sync(0xffffffffu, t, o);
            if (lane >= o) t += y;
        }
        if (lane < NW) ws[lane] = t;
    }
    __syncthreads();
    unsigned base = w ? ws[w-1] : 0u;
    *tot = ws[NW - 1];
    __syncthreads();
    return base + x - v;
}

template<int NT>
__device__ __forceinline__ unsigned long long blk_exscan_u64(unsigned long long v, int tid,
                                                             unsigned long long* tot)
{
    constexpr int NW = NT/32;
    __shared__ unsigned long long ws[NW];
    int lane = tid & 31, w = tid >> 5;
    unsigned long long x = v;
#pragma unroll
    for (int o = 1; o < 32; o <<= 1) {
        unsigned long long y = __shfl_up_sync(0xffffffffu, x, o);
        if (lane >= o) x += y;
    }
    if (lane == 31) ws[w] = x;
    __syncthreads();
    if (w == 0) {
        unsigned long long t = (lane < NW) ? ws[lane] : 0ull;
#pragma unroll
        for (int o = 1; o < NW; o <<= 1) {
            unsigned long long y = __shfl_up_sync(0xffffffffu, t, o);
            if (lane >= o) t += y;
        }
        if (lane < NW) ws[lane] = t;
    }
    __syncthreads();
    unsigned long long base = w ? ws[w-1] : 0ull;
    *tot = ws[NW - 1];
    __syncthreads();
    return base + x - v;
}

// last-block-done: returns true in exactly one block after all blocks arrive.
__device__ __forceinline__ bool last_block(unsigned* ctr, unsigned nb)
{
    __shared__ unsigned s_last;
    __threadfence();
    __syncthreads();
    if (threadIdx.x == 0) {
        unsigned prev = atomicAdd(ctr, 1u);
        if (prev == nb - 1u) { *ctr = 0u; s_last = 1u; }   // self-reset for replay
        else                 s_last = 0u;
    }
    __syncthreads();
    return s_last != 0u;
}

// ---------------- kernel 1: per-vertex prep + occ bit-pack + interleaved float4 ----------------
__global__ void k_prep(const float* __restrict__ feats,
                       const float* __restrict__ sdf_n,
                       const float* __restrict__ dir,
                       const float* __restrict__ rotm,
                       const float* __restrict__ scales,
                       int N, float dscale)
{
    int v = blockIdx.x*blockDim.x + threadIdx.x;
    bool inb = v < N;
    float s = inb ? sdf_n[v] : -1.0f;
    unsigned bal = __ballot_sync(0xffffffffu, s > 0.0f);
    if ((threadIdx.x & 31) == 0) g_occw[v >> 5] = bal;
    if (!inb) return;

    float ts = tanhf(s);
    float l0 = dscale * tanhf(dir[2*v+0]);
    float l1 = dscale * tanhf(dir[2*v+1]);
    const float* m = rotm + 9*(size_t)v;
    float sc = scales[v];
    const float* f = feats + (size_t)v * 6;
    g_vab[2*v]   = make_float4((m[0]*l0 + m[3]*l1 + m[6]) * sc,
                               (m[1]*l0 + m[4]*l1 + m[7]) * sc,
                               (m[2]*l0 + m[5]*l1 + m[8]) * sc, ts);
    g_vab[2*v+1] = make_float4(f[3], f[4], f[5], 0.0f);
}

// ---------------- kernel 2: edge-group masks + counts (+cube codes if NCeff>0) ----------------
__global__ void k_grp(int N, int S, int NG, int NCeff, int R)
{
    int t = blockIdx.x*blockDim.x + threadIdx.x;
    int S2 = S*S;

    if (t < NG) {
        int v0 = t << 5;
        int i0 = v0 / S2; int rem = v0 - i0*S2; int j0 = rem / S; int k0 = rem - j0*S;
        int qw = S - k0;
        unsigned pre = (qw >= 32) ? 0xffffffffu : ((1u << (qw & 31)) - 1u);
        int j1 = j0 + 1, i1 = i0; if (j1 == S) { j1 = 0; ++i1; }
        int nvld = N - v0;
        unsigned tailm = (nvld >= 32) ? 0xffffffffu : ((1u << (nvld & 31)) - 1u);
        unsigned A = bits32(v0);
        unsigned mm[7]; int cnt = 0;
#pragma unroll
        for (int tt = 1; tt <= 7; ++tt) {
            int di = (tt>>2)&1, dj = (tt>>1)&1, dk = tt&1;
            int d = di*S2 + dj*S + dk;
            unsigned X = A ^ bits32(v0 + d);
            unsigned vm = (((i0+di < S) && (j0+dj < S)) ? pre : 0u)
                        | (((i1+di < S) && (j1+dj < S)) ? ~pre : 0u);
            if (dk && (qw - 1) < 32) vm &= ~(1u << (qw - 1));
            vm &= tailm;
            mm[tt-1] = X & vm;
            cnt += __popc(mm[tt-1]);
        }
        g_egrp[2*t]   = make_uint4(mm[0], mm[1], mm[2], mm[3]);
        g_egrp[2*t+1] = make_uint4(mm[4], mm[5], mm[6], 0u);
        g_eGrpCnt[t]  = cnt;
    }

    if (t < NCeff) {          // generic fallback only (fast path computes codes in k_rankscan)
        int R2 = R*R;
        int i = t / R2; int rem = t - i*R2; int j = rem / R; int k = rem - j*R;
        int b = (i*S + j)*S + k;
        unsigned p00 = bits32(b)          & 3u;
        unsigned p01 = bits32(b + S)      & 3u;
        unsigned p10 = bits32(b + S2)     & 3u;
        unsigned p11 = bits32(b + S2 + S) & 3u;
        g_cubeCode[t] = (unsigned char)(p00 | (p01 << 2) | (p10 << 4) | (p11 << 6));
    }

    // last arriving block: exclusive scan over group counts + build d_triE
    if (last_block(&g_done1, gridDim.x)) {
        int tid = threadIdx.x;
        if (tid < 96) {
            int p = tid >> 4, ti = tid & 15;
            unsigned pk = 0u;
            for (int q = 0; q < 6; ++q) {
                int sl = c_tri[ti][q];
                int e  = (sl >= 0) ? c_s2e[p][sl] : 0;
                pk |= (unsigned)e << (5*q);
            }
            d_triE[tid] = pk;
        }
        int K = (NG + SCAN_B - 1) / SCAN_B;
        int base = tid * K;
        int run = 0;
        for (int it = 0; it < K; ++it) {
            int idx = base + it;
            if (idx < NG) run += g_eGrpCnt[idx];
        }
        unsigned tot;
        unsigned exc = blk_exscan_u32<SCAN_B>((unsigned)run, tid, &tot);
        int acc = (int)exc;
        for (int it = 0; it < K; ++it) {
            int idx = base + it;
            if (idx < NG) {
                int c = g_eGrpCnt[idx];
                ((unsigned*)g_egrp)[idx*8 + 7] = (unsigned)acc;
                acc += c;
            }
        }
        if (tid == 0) g_nv = (int)tot;
    }
}

// ---------------- kernel 3: rank table + edge list + tet scan (+cube codes fast) ----------------
__global__ void k_rankscan(int NG, int nRB, int T, int R, int nCh, int S,
                           int rbR, int fastT)
{
    int tid = threadIdx.x;
    int S2 = S*S;

    if (blockIdx.x < nRB) {
        // ---- one warp per 32-anchor group: compute ranks ----
        int g = blockIdx.x*8 + (tid >> 5);
        if (g < NG) {
            int lane = tid & 31;
            uint4 Aa = g_egrp[2*g], Bb = g_egrp[2*g+1];
            unsigned mm[7] = {Aa.x, Aa.y, Aa.z, Aa.w, Bb.x, Bb.y, Bb.z};
            unsigned low = (1u << lane) - 1u;
            int cum = (int)Bb.w;
#pragma unroll
            for (int x = 0; x < 7; ++x) cum += __popc(mm[x] & low);
            int v = (g << 5) + lane;
            int part = 0;
#pragma unroll
            for (int t = 0; t < 7; ++t) {
                if ((mm[t] >> lane) & 1u) {
                    int rank = cum + part; ++part;
                    g_edgeRank[t*NMAXV + v] = rank;
                    g_edgeList[rank] = (v << 3) | (t + 1);
                }
            }
        }
    } else if (fastT) {
        // ---- FAST tet path: uniform perm per chunk; codes from occ bits ----
        int ch = blockIdx.x - nRB;
        int base = ch*TCH + tid*SCAN_I;        // multiple of 8
        int p  = base >> (3*rbR);
        int c0 = base & ((1 << (3*rbR)) - 1);
        int i  = c0 >> (2*rbR);
        int rem = c0 & ((1 << (2*rbR)) - 1);
        int j = rem >> rbR, k = rem & (R - 1);
        int b = (i*S + j)*S + k;
        unsigned w00 = bits32(b), w01 = bits32(b + S);
        unsigned w10 = bits32(b + S2), w11 = bits32(b + S2 + S);
        int P0 = c_path[p][0], P1 = c_path[p][1], P2 = c_path[p][2], P3 = c_path[p][3];
        unsigned codes0 = 0u, codes1 = 0u;
        unsigned loc[SCAN_I], sum = 0u;
#pragma unroll
        for (int x = 0; x < SCAN_I; ++x) {
            unsigned code = ((w00 >> x) & 3u) | (((w01 >> x) & 3u) << 2)
                          | (((w10 >> x) & 3u) << 4) | (((w11 >> x) & 3u) << 6);
            if (x < 4) codes0 |= code << (8*x); else codes1 |= code << (8*(x-4));
            int ti = ((code >> P0) & 1) | (((code >> P1) & 1) << 1)
                   | (((code >> P2) & 1) << 2) | (((code >> P3) & 1) << 3);
            int nt = (int)((NT_PACK >> (ti << 1)) & 3u);
            unsigned add = (unsigned)(nt & 1) | ((unsigned)(nt >> 1) << 16);
            loc[x] = sum; sum += add;
        }
        if (p == 0) *(uint2*)(g_cubeCode + c0) = make_uint2(codes0, codes1);
        unsigned tot;
        unsigned exc = blk_exscan_u32<SCAN_B>(sum, tid, &tot);
#pragma unroll
        for (int x = 0; x < SCAN_I; ++x) g_tetScan[base + x] = exc + loc[x];
        if (tid == SCAN_B-1) g_tBlkP[ch] = tot;
    } else {
        // ---- generic tet path (cubeCode from k_grp) ----
        int ch = blockIdx.x - nRB;
        int base = ch*TCH + tid*SCAN_I;
        int R3 = R*R*R;
        unsigned loc[SCAN_I], sum = 0u;
#pragma unroll
        for (int it = 0; it < SCAN_I; ++it) {
            int r = base + it;
            unsigned add = 0u;
            if (r < T) {
                int p = r / R3, c = r - p*R3;
                unsigned code = g_cubeCode[c];
                int ti = ((code >> c_path[p][0]) & 1)
                       | (((code >> c_path[p][1]) & 1) << 1)
                       | (((code >> c_path[p][2]) & 1) << 2)
                       | (((code >> c_path[p][3]) & 1) << 3);
                int nt = (int)((NT_PACK >> (ti << 1)) & 3u);
                add = (unsigned)(nt & 1) | ((unsigned)(nt >> 1) << 16);
            }
            loc[it] = sum; sum += add;
        }
        unsigned tot;
        unsigned exc = blk_exscan_u32<SCAN_B>(sum, tid, &tot);
#pragma unroll
        for (int it = 0; it < SCAN_I; ++it) {
            int r = base + it;
            if (r < T) g_tetScan[r] = exc + loc[it];
        }
        if (tid == SCAN_B-1) g_tBlkP[ch] = tot;
    }

    // last arriving block: exclusive scan of chunk sums
    if (last_block(&g_done2, gridDim.x)) {
        int K = (nCh + SCAN_B - 1) / SCAN_B;
        int b0 = tid * K;
        unsigned long long run = 0ull;
        for (int it = 0; it < K; ++it) {
            int idx = b0 + it;
            if (idx < nCh) {
                unsigned pkt = g_tBlkP[idx];
                run += (unsigned long long)(pkt & 0xffffu)
                     + ((unsigned long long)(pkt >> 16) << 32);
            }
        }
        unsigned long long tot64;
        unsigned long long exc64 = blk_exscan_u64<SCAN_B>(run, tid, &tot64);
        unsigned long long acc = exc64;
        for (int it = 0; it < K; ++it) {
            int idx = b0 + it;
            if (idx < nCh) {
                unsigned pkt = g_tBlkP[idx];
                g_tBlk64[idx] = acc;
                acc += (unsigned long long)(pkt & 0xffffu)
                     + ((unsigned long long)(pkt >> 16) << 32);
            }
        }
        if (tid == 0) g_n1 = (int)(tot64 & 0xffffffffull);
    }
}

// ---------------- kernel 4: fused emit — verts (rank-dense) | faces (cube-centric) ----------------
__global__ void k_emit(float* __restrict__ out,
                       int nVB, int NC, int R, int S, int rbR, int R3)
{
    __shared__ int ser[SCAN_B * 19];     // face path; vertex path reuses first 6KB
    int tid = threadIdx.x;
    int S2 = S*S;

    if (blockIdx.x < nVB) {
        // ===== vertex emit: thread-per-output-vertex, smem-staged dense stores =====
        float* sm = (float*)ser;
        int nv = g_nv;
        int b0 = blockIdx.x * SCAN_B;
        if (b0 >= nv) return;
        int cnt = nv - b0; if (cnt > SCAN_B) cnt = SCAN_B;
        int idx = b0 + tid;
        if (tid < cnt) {
            int packed = g_edgeList[idx];
            int v = packed >> 3, t = packed & 7;
            int v2 = v + ((t>>2)&1)*S2 + ((t>>1)&1)*S + (t&1);
            float4 A  = g_vab[2*v];
            float4 B  = g_vab[2*v+1];
            float4 A2 = g_vab[2*v2];
            float4 B2 = g_vab[2*v2+1];
            float inv = 1.0f / (A.w - A2.w);
            float wa = -A2.w * inv, wb = A.w * inv;
            float* o = sm + tid*6;
            o[0] = wa*A.x + wb*A2.x;
            o[1] = wa*A.y + wb*A2.y;
            o[2] = wa*A.z + wb*A2.z;
            o[3] = wa*B.x + wb*B2.x;
            o[4] = wa*B.y + wb*B2.y;
            o[5] = wa*B.z + wb*B2.z;
        }
        __syncthreads();
        float2* dst = (float2*)(out + (size_t)b0 * 6);
        const float2* src = (const float2*)sm;
        int nf2 = 3 * cnt;
        for (int i = tid; i < nf2; i += SCAN_B) dst[i] = src[i];
        return;
    }

    // ===== faces: one thread per CUBE (19 shared edges) =====
    int c = (blockIdx.x - nVB)*SCAN_B + tid;
    if (c >= NC) return;

    unsigned code = g_cubeCode[c];
    int tis[6], nts[6]; int total = 0;
#pragma unroll
    for (int p = 0; p < 6; ++p) {
        int ti = ((code >> c_path[p][0]) & 1) | (((code >> c_path[p][1]) & 1) << 1)
               | (((code >> c_path[p][2]) & 1) << 2) | (((code >> c_path[p][3]) & 1) << 3);
        tis[p] = ti;
        int nt = (int)((NT_PACK >> (ti << 1)) & 3u);
        nts[p] = nt; total += nt;
    }
    if (!total) return;

    int i, j, k;
    if (rbR >= 0) {
        i = c >> (2*rbR); int rem = c & ((1 << (2*rbR)) - 1);
        j = rem >> rbR;   k = rem & (R - 1);
    } else {
        int R2 = R*R;
        i = c / R2; int rem = c - i*R2; j = rem / R; k = rem - j*R;
    }
    int v000 = (i*S + j)*S + k;
    int uo[7] = {0, 1, S, S+1, S2, S2+1, S2+S};
    const int eu[19] = {0,0,0,0,0,0,0, 1,1,1, 2,2,2, 3, 4,4,4, 5, 6};
    const int et[19] = {0,1,2,3,4,5,6, 1,3,5, 0,3,4, 3, 0,1,2, 1, 0};
    int* my = ser + tid*19;
#pragma unroll
    for (int x = 0; x < 19; ++x)
        my[x] = g_edgeRank[et[x]*NMAXV + v000 + uo[eu[x]]];

    size_t vbase = (size_t)g_nv * 6;
    int n1 = g_n1;
#pragma unroll
    for (int p = 0; p < 6; ++p) {
        int nt = nts[p];
        if (!nt) continue;
        int r = p*R3 + c;
        unsigned sc = g_tetScan[r];
        unsigned long long bk = g_tBlk64[r / TCH];
        int s1 = (int)(sc & 0xffffu) + (int)(unsigned)(bk & 0xffffffffull);
        int s2 = (int)(sc >> 16)     + (int)(unsigned)(bk >> 32);
        unsigned epk = d_triE[(p << 4) + tis[p]];
        size_t o = (nt == 1) ? vbase + (size_t)s1 * 3
                             : vbase + ((size_t)n1 + 2*(size_t)s2) * 3;
        out[o+0] = (float)my[ epk        & 31u];
        out[o+1] = (float)my[(epk >> 5)  & 31u];
        out[o+2] = (float)my[(epk >> 10) & 31u];
        if (nt == 2) {
            out[o+3] = (float)my[(epk >> 15) & 31u];
            out[o+4] = (float)my[(epk >> 20) & 31u];
            out[o+5] = (float)my[(epk >> 25) & 31u];
        }
    }
}

// ---------------- launch ----------------
extern "C" void kernel_launch(void* const* d_in, const int* in_sizes, int n_in,
                              void* d_out, int out_size)
{
    const float* feats  = (const float*)d_in[0];
    const float* sdf_n  = (const float*)d_in[1];
    const float* dir    = (const float*)d_in[2];
    const float* rotm   = (const float*)d_in[3];
    const float* scales = (const float*)d_in[4];

    int N = in_sizes[1];
    int S = 1;
    while ((long long)S*S*S < (long long)N) ++S;   // S = R+1
    int R = S - 1;
    int E = 7*N;
    int T = 6*R*R*R;
    int NC = R*R*R;
    int NG = (N + 31) >> 5;
    int nCh = (T + TCH - 1) / TCH;
    float dscale = 4.0f / (float)R;
    float* out = (float*)d_out;

    int rbR = -1;
    if ((R & (R-1)) == 0) { rbR = 0; while ((1 << rbR) < R) ++rbR; }
    int R3 = R*R*R;
    int fastT = (rbR >= 0 && (R3 % TCH) == 0 && (R % 8) == 0) ? 1 : 0;

    int NCeff = fastT ? 0 : NC;                    // cube codes in k_grp only if generic
    int ngrp  = fastT ? NG : ((NC > NG) ? NC : NG);
    int nRB   = (NG + 7) / 8;                      // rank blocks (8 warps/block)
    int nVB   = (E + SCAN_B - 1) / SCAN_B;         // vertex-emit blocks (covers worst case)
    int nCB   = (NC + SCAN_B - 1) / SCAN_B;        // cube blocks for faces

    k_prep    <<<(N + 255)/256, 256>>>(feats, sdf_n, dir, rotm, scales, N, dscale);
    k_grp     <<<(ngrp + 255)/256, 256>>>(N, S, NG, NCeff, R);
    k_rankscan<<<nRB + nCh, SCAN_B>>>(NG, nRB, T, R, nCh, S, rbR, fastT);
    k_emit    <<<nVB + nCB, SCAN_B>>>(out, nVB, NC, R, S, rbR, R3);
}